// round 1
// baseline (speedup 1.0000x reference)
#include <cuda_runtime.h>

#define B_   32
#define C_   128
#define N_   1024   // L*L
#define H_   8
#define DK_  64
#define HD_  512    // H*DK
#define R3_  1536   // 3*HD

// Scratch (allocation-free contract: __device__ globals)
__device__ float g_qkv[(size_t)B_ * R3_ * N_];   // [b][r][n], r: 0..511=Q, 512..1023=K, 1024..1535=V
__device__ float g_att[(size_t)B_ * N_ * HD_];   // [b][n][h*64+d]

// ---------------------------------------------------------------------------
// Kernel A: QKV projection.  out[b][r][n] = W[r][:] . (x[b][:][n] * inv_layer)
// ---------------------------------------------------------------------------
__global__ __launch_bounds__(256) void qkv_kernel(
    const float* __restrict__ x,
    const float* __restrict__ Wq,
    const float* __restrict__ Wk,
    const float* __restrict__ Wv)
{
    const float inv_layer = 0.44721359549995793f;  // 1/sqrt(5)
    int tid = threadIdx.x;
    int tx = tid & 15, ty = tid >> 4;
    int n0 = blockIdx.x * 64;
    int r0 = blockIdx.y * 64;
    int b  = blockIdx.z;

    const float* W = (r0 < HD_) ? Wq : (r0 < 2 * HD_) ? Wk : Wv;
    int rw0 = r0 & (HD_ - 1);

    __shared__ float Ws[64][65];   // [r][k]
    __shared__ float Xs[64][64];   // [k][n] (float4 reads)

    float acc[4][4] = {};
    const float* xb = x + (size_t)b * C_ * N_;

    #pragma unroll
    for (int kc = 0; kc < 2; kc++) {
        int k0 = kc * 64;
        #pragma unroll
        for (int t = 0; t < 16; t++) {
            int e = tid + t * 256;
            int rr = e >> 6, kk = e & 63;
            Ws[rr][kk] = W[(rw0 + rr) * C_ + k0 + kk];
        }
        #pragma unroll
        for (int t = 0; t < 16; t++) {
            int e = tid + t * 256;
            int kk = e >> 6, nn = e & 63;
            Xs[kk][nn] = xb[(k0 + kk) * N_ + n0 + nn] * inv_layer;
        }
        __syncthreads();
        #pragma unroll
        for (int k = 0; k < 64; k++) {
            float4 bv = *(const float4*)&Xs[k][tx * 4];
            float bb[4] = {bv.x, bv.y, bv.z, bv.w};
            float aa[4];
            #pragma unroll
            for (int m = 0; m < 4; m++) aa[m] = Ws[ty * 4 + m][k];
            #pragma unroll
            for (int m = 0; m < 4; m++)
                #pragma unroll
                for (int n = 0; n < 4; n++)
                    acc[m][n] += aa[m] * bb[n];
        }
        __syncthreads();
    }

    float* outb = g_qkv + (size_t)b * R3_ * N_;
    #pragma unroll
    for (int m = 0; m < 4; m++) {
        float4 v = make_float4(acc[m][0], acc[m][1], acc[m][2], acc[m][3]);
        *(float4*)&outb[(size_t)(r0 + ty * 4 + m) * N_ + n0 + tx * 4] = v;
    }
}

// ---------------------------------------------------------------------------
// Kernel B: fused attention per (query-tile=64, head, batch).
//   S[i][j] = (sum_d Q[d,i]K[d,j] + bias(i,j)) * 0.125
//   online softmax over j; O[i][d] = sum_j P[i][j] V[d][j]; store O/l.
// ---------------------------------------------------------------------------
__global__ __launch_bounds__(256) void attn_kernel(const float* __restrict__ R)
{
    int tid = threadIdx.x;
    int tx = tid & 15, ty = tid >> 4;
    int q0 = blockIdx.x * 64;
    int h  = blockIdx.y;
    int b  = blockIdx.z;

    __shared__ float Qs[64][64];   // [d][i]  16 KB
    __shared__ float Ks[64][32];   // [d][j]   8 KB
    __shared__ float Vs[64][33];   // [d][j]   8.25 KB (pad: conflict-free col reads)
    __shared__ float Ps[64][33];   // [i][j]   8.25 KB
    __shared__ float Rs[1024];     //           4 KB
    // total 45568 B < 48 KB static limit

    const float* qkv_b = g_qkv + (size_t)b * R3_ * N_;
    const float* Qg = qkv_b + (size_t)(h * DK_) * N_;
    const float* Kg = qkv_b + (size_t)(HD_ + h * DK_) * N_;
    const float* Vg = qkv_b + (size_t)(2 * HD_ + h * DK_) * N_;

    #pragma unroll
    for (int t = 0; t < 16; t++) {
        int e = tid + t * 256;
        int d = e >> 6, i = e & 63;
        Qs[d][i] = Qg[(size_t)d * N_ + q0 + i];
    }
    #pragma unroll
    for (int t = 0; t < 4; t++)
        Rs[tid + t * 256] = R[h * 1024 + tid + t * 256];

    float m[4], l[4], o[4][4];
    #pragma unroll
    for (int ii = 0; ii < 4; ii++) {
        m[ii] = -1e30f; l[ii] = 0.0f;
        #pragma unroll
        for (int dd = 0; dd < 4; dd++) o[ii][dd] = 0.0f;
    }

    for (int j0 = 0; j0 < N_; j0 += 32) {
        __syncthreads();  // protect Ks/Vs/Ps from previous iteration's readers
        #pragma unroll
        for (int t = 0; t < 8; t++) {
            int e = tid + t * 256;
            int d = e >> 5, j = e & 31;
            Ks[d][j] = Kg[(size_t)d * N_ + j0 + j];
            Vs[d][j] = Vg[(size_t)d * N_ + j0 + j];
        }
        __syncthreads();

        // S = Q^T K  (64 queries x 32 keys, each thread 4x2)
        float s[4][2] = {};
        #pragma unroll
        for (int d = 0; d < 64; d++) {
            float4 qv = *(const float4*)&Qs[d][ty * 4];
            float2 kv = *(const float2*)&Ks[d][tx * 2];
            float qa[4] = {qv.x, qv.y, qv.z, qv.w};
            float kb[2] = {kv.x, kv.y};
            #pragma unroll
            for (int ii = 0; ii < 4; ii++)
                #pragma unroll
                for (int jj = 0; jj < 2; jj++)
                    s[ii][jj] += qa[ii] * kb[jj];
        }

        // bias + scale + online softmax (row reductions across 16 tx lanes)
        #pragma unroll
        for (int ii = 0; ii < 4; ii++) {
            int ig = q0 + ty * 4 + ii;
            int i1 = ig >> 5, i2 = ig & 31;
            float sb[2];
            #pragma unroll
            for (int jj = 0; jj < 2; jj++) {
                int jg = j0 + tx * 2 + jj;
                int j1 = jg >> 5, j2 = jg & 31;
                sb[jj] = (s[ii][jj] + Rs[((i1 - j1) & 31) * 32 + ((i2 - j2) & 31)]) * 0.125f;
            }
            float mx = fmaxf(sb[0], sb[1]);
            #pragma unroll
            for (int off = 1; off < 16; off <<= 1)
                mx = fmaxf(mx, __shfl_xor_sync(0xffffffffu, mx, off, 16));
            float mn = fmaxf(m[ii], mx);
            float f  = __expf(m[ii] - mn);
            float p0 = __expf(sb[0] - mn);
            float p1 = __expf(sb[1] - mn);
            float rs = p0 + p1;
            #pragma unroll
            for (int off = 1; off < 16; off <<= 1)
                rs += __shfl_xor_sync(0xffffffffu, rs, off, 16);
            l[ii] = l[ii] * f + rs;
            m[ii] = mn;
            #pragma unroll
            for (int dd = 0; dd < 4; dd++) o[ii][dd] *= f;
            Ps[ty * 4 + ii][tx * 2 + 0] = p0;
            Ps[ty * 4 + ii][tx * 2 + 1] = p1;
        }
        __syncthreads();

        // O += P * V^T   (thread owns rows i=ty*4+ii, cols d=dd*16+tx)
        #pragma unroll
        for (int j = 0; j < 32; j++) {
            float pp[4], vv[4];
            #pragma unroll
            for (int ii = 0; ii < 4; ii++) pp[ii] = Ps[ty * 4 + ii][j];
            #pragma unroll
            for (int dd = 0; dd < 4; dd++) vv[dd] = Vs[dd * 16 + tx][j];
            #pragma unroll
            for (int ii = 0; ii < 4; ii++)
                #pragma unroll
                for (int dd = 0; dd < 4; dd++)
                    o[ii][dd] += pp[ii] * vv[dd];
        }
    }

    float* ab = g_att + (size_t)b * N_ * HD_;
    #pragma unroll
    for (int ii = 0; ii < 4; ii++) {
        float inv = 1.0f / l[ii];
        #pragma unroll
        for (int dd = 0; dd < 4; dd++)
            ab[(size_t)(q0 + ty * 4 + ii) * HD_ + h * DK_ + dd * 16 + tx] = o[ii][dd] * inv;
    }
}

// ---------------------------------------------------------------------------
// Kernel C: out[b][c][n] = sum_r W0[c][r] * att[b][n][r] + x[b][c][n]
// ---------------------------------------------------------------------------
__global__ __launch_bounds__(256) void out_kernel(
    const float* __restrict__ W0,
    const float* __restrict__ x,
    float* __restrict__ out)
{
    int tid = threadIdx.x;
    int tx = tid & 15, ty = tid >> 4;
    int n0 = blockIdx.x * 64;
    int c0 = blockIdx.y * 64;
    int b  = blockIdx.z;

    __shared__ float As[64][65];   // [c][k]
    __shared__ float Bs[64][65];   // [n][k]

    float acc[4][4] = {};
    const float* ab = g_att + (size_t)b * N_ * HD_;

    for (int k0 = 0; k0 < HD_; k0 += 64) {
        #pragma unroll
        for (int t = 0; t < 16; t++) {
            int e = tid + t * 256;
            int cc = e >> 6, kk = e & 63;
            As[cc][kk] = W0[(c0 + cc) * HD_ + k0 + kk];
        }
        #pragma unroll
        for (int t = 0; t < 16; t++) {
            int e = tid + t * 256;
            int nn = e >> 6, kk = e & 63;
            Bs[nn][kk] = ab[(size_t)(n0 + nn) * HD_ + k0 + kk];
        }
        __syncthreads();
        #pragma unroll
        for (int k = 0; k < 64; k++) {
            float aa[4], bb[4];
            #pragma unroll
            for (int ii = 0; ii < 4; ii++) aa[ii] = As[ty * 4 + ii][k];
            #pragma unroll
            for (int jj = 0; jj < 4; jj++) bb[jj] = Bs[tx * 4 + jj][k];
            #pragma unroll
            for (int ii = 0; ii < 4; ii++)
                #pragma unroll
                for (int jj = 0; jj < 4; jj++)
                    acc[ii][jj] += aa[ii] * bb[jj];
        }
        __syncthreads();
    }

    const float* xb = x + (size_t)b * C_ * N_;
    float* ob = out + (size_t)b * C_ * N_;
    #pragma unroll
    for (int ii = 0; ii < 4; ii++) {
        int row = c0 + ty * 4 + ii;
        float4 xv = *(const float4*)&xb[(size_t)row * N_ + n0 + tx * 4];
        float4 r;
        r.x = acc[ii][0] + xv.x;
        r.y = acc[ii][1] + xv.y;
        r.z = acc[ii][2] + xv.z;
        r.w = acc[ii][3] + xv.w;
        *(float4*)&ob[(size_t)row * N_ + n0 + tx * 4] = r;
    }
}

// ---------------------------------------------------------------------------
extern "C" void kernel_launch(void* const* d_in, const int* in_sizes, int n_in,
                              void* d_out, int out_size)
{
    const float* x  = (const float*)d_in[0];
    const float* Wq = (const float*)d_in[1];
    const float* Wk = (const float*)d_in[2];
    const float* Wv = (const float*)d_in[3];
    const float* R  = (const float*)d_in[4];
    const float* W0 = (const float*)d_in[5];
    float* out = (float*)d_out;

    qkv_kernel<<<dim3(16, 24, 32), 256>>>(x, Wq, Wk, Wv);
    attn_kernel<<<dim3(16, 8, 32), 256>>>(R);
    out_kernel<<<dim3(16, 2, 32), 256>>>(W0, x, out);
}

// round 2
// speedup vs baseline: 3.0205x; 3.0205x over previous
#include <cuda_runtime.h>
#include <cstdint>

#define B_   32
#define C_   128
#define N_   1024   // L*L
#define H_   8
#define DK_  64
#define HD_  512    // H*DK
#define R3_  1536   // 3*HD
#define FULL 0xffffffffu

// Scratch (allocation-free contract: __device__ globals)
__device__ float g_qkv[(size_t)B_ * R3_ * N_];   // [b][r][n] (tf32-rounded)
__device__ float g_att[(size_t)B_ * N_ * HD_];   // [b][n][h*64+d] (tf32-rounded)

__device__ __forceinline__ float to_tf32(float x) {
    float y;
    asm("cvt.rna.tf32.f32 %0, %1;" : "=f"(y) : "f"(x));
    return y;
}

__device__ __forceinline__ void mma_tf32(
    float& d0, float& d1, float& d2, float& d3,
    uint32_t a0, uint32_t a1, uint32_t a2, uint32_t a3,
    uint32_t b0, uint32_t b1)
{
    asm volatile(
        "mma.sync.aligned.m16n8k8.row.col.f32.tf32.tf32.f32 "
        "{%0,%1,%2,%3},{%4,%5,%6,%7},{%8,%9},{%0,%1,%2,%3};"
        : "+f"(d0), "+f"(d1), "+f"(d2), "+f"(d3)
        : "r"(a0), "r"(a1), "r"(a2), "r"(a3), "r"(b0), "r"(b1));
}

// ---------------------------------------------------------------------------
// Kernel A: QKV projection.  g_qkv[b][r][n] = tf32( W[r] . (x[b][:][n]*s) )
// Block tile 128(r) x 128(n), K=128 in 4 chunks of 32. 8 warps = 4(m) x 2(n).
// ---------------------------------------------------------------------------
__global__ __launch_bounds__(256) void qkv_kernel(
    const float* __restrict__ x,
    const float* __restrict__ Wq,
    const float* __restrict__ Wk,
    const float* __restrict__ Wv)
{
    const float inv_layer = 0.44721359549995793f;  // 1/sqrt(5)
    int tid = threadIdx.x;
    int lane = tid & 31, w = tid >> 5;
    int g = lane >> 2, tg = lane & 3;
    int mw = w & 3, nw = w >> 2;
    int n0 = blockIdx.x * 128;
    int r0 = blockIdx.y * 128;
    int b  = blockIdx.z;

    const float* W = (r0 < HD_) ? Wq : (r0 < 2 * HD_) ? Wk : Wv;
    int rw0 = r0 & (HD_ - 1);
    const float* xb = x + (size_t)b * C_ * N_;

    __shared__ float Ws[128][36];   // [m][k], stride 36 (≡4 mod 32)
    __shared__ float Xs[32][136];   // [k][n], stride 136 (≡8 mod 32)

    float acc[2][8][4];
    #pragma unroll
    for (int i = 0; i < 2; i++)
        #pragma unroll
        for (int j = 0; j < 8; j++)
            #pragma unroll
            for (int k = 0; k < 4; k++) acc[i][j][k] = 0.0f;

    for (int kc = 0; kc < 4; kc++) {
        __syncthreads();
        #pragma unroll
        for (int t = 0; t < 16; t++) {
            int e = tid + t * 256;
            int k = e & 31, m = e >> 5;
            Ws[m][k] = to_tf32(W[(rw0 + m) * C_ + kc * 32 + k]);
        }
        #pragma unroll
        for (int t = 0; t < 16; t++) {
            int e = tid + t * 256;
            int n = e & 127, c = e >> 7;
            Xs[c][n] = to_tf32(xb[(size_t)(kc * 32 + c) * N_ + n0 + n] * inv_layer);
        }
        __syncthreads();

        #pragma unroll
        for (int ks = 0; ks < 32; ks += 8) {
            uint32_t a[2][4];
            #pragma unroll
            for (int mt = 0; mt < 2; mt++) {
                int row = mw * 32 + mt * 16;
                a[mt][0] = __float_as_uint(Ws[row + g][ks + tg]);
                a[mt][1] = __float_as_uint(Ws[row + 8 + g][ks + tg]);
                a[mt][2] = __float_as_uint(Ws[row + g][ks + tg + 4]);
                a[mt][3] = __float_as_uint(Ws[row + 8 + g][ks + tg + 4]);
            }
            #pragma unroll
            for (int nt = 0; nt < 8; nt++) {
                int col = nw * 64 + nt * 8 + g;
                uint32_t b0 = __float_as_uint(Xs[ks + tg][col]);
                uint32_t b1 = __float_as_uint(Xs[ks + tg + 4][col]);
                #pragma unroll
                for (int mt = 0; mt < 2; mt++)
                    mma_tf32(acc[mt][nt][0], acc[mt][nt][1], acc[mt][nt][2], acc[mt][nt][3],
                             a[mt][0], a[mt][1], a[mt][2], a[mt][3], b0, b1);
            }
        }
    }

    float* outb = g_qkv + (size_t)b * R3_ * N_;
    #pragma unroll
    for (int mt = 0; mt < 2; mt++) {
        int row_a = r0 + mw * 32 + mt * 16 + g;
        #pragma unroll
        for (int nt = 0; nt < 8; nt++) {
            int col = n0 + nw * 64 + nt * 8 + 2 * tg;
            float2 va = make_float2(to_tf32(acc[mt][nt][0]), to_tf32(acc[mt][nt][1]));
            *(float2*)&outb[(size_t)row_a * N_ + col] = va;
            float2 vb = make_float2(to_tf32(acc[mt][nt][2]), to_tf32(acc[mt][nt][3]));
            *(float2*)&outb[(size_t)(row_a + 8) * N_ + col] = vb;
        }
    }
}

// ---------------------------------------------------------------------------
// Kernel B: flash attention, block = (i-tile 128, head, batch), 8 warps.
// Each warp owns 16 query rows. j-step = 64 keys. mma tf32 for QK^T and PV.
// ---------------------------------------------------------------------------
__global__ __launch_bounds__(256, 2) void attn_kernel(const float* __restrict__ R)
{
    extern __shared__ float sm[];
    float* Qs = sm;                    // [128][68]
    float* Ks = Qs + 128 * 68;         // [64][68]  ([j][d])
    float* Vs = Ks + 64 * 68;          // [64][68]  ([d][j])
    float* Rs = Vs + 64 * 68;          // [1024]

    int tid = threadIdx.x;
    int lane = tid & 31, w = tid >> 5;
    int g = lane >> 2, tg = lane & 3;
    int i0 = blockIdx.x * 128;
    int h  = blockIdx.y;
    int b  = blockIdx.z;
    int m0 = w * 16;

    const float* qkv_b = g_qkv + (size_t)b * R3_ * N_;
    const float* Qg = qkv_b + (size_t)(h * DK_) * N_;
    const float* Kg = qkv_b + (size_t)(HD_ + h * DK_) * N_;
    const float* Vg = qkv_b + (size_t)(2 * HD_ + h * DK_) * N_;

    // Q tile [i][d] (transposed from [d][n] global)
    #pragma unroll
    for (int t = 0; t < 32; t++) {
        int e = tid + t * 256;
        int i = e & 127, d = e >> 7;
        Qs[i * 68 + d] = Qg[(size_t)d * N_ + i0 + i];
    }
    #pragma unroll
    for (int t = 0; t < 4; t++)
        Rs[tid + t * 256] = R[h * 1024 + tid + t * 256];

    float o[8][4];
    #pragma unroll
    for (int dt = 0; dt < 8; dt++)
        #pragma unroll
        for (int r = 0; r < 4; r++) o[dt][r] = 0.0f;
    float mA = -1e30f, mB = -1e30f, lA = 0.0f, lB = 0.0f;

    int i_a = i0 + m0 + g;
    int i_b = i_a + 8;
    int i1a = i_a >> 5, i2a = i_a & 31;
    int i1b = i_b >> 5, i2b = i_b & 31;

    for (int j0 = 0; j0 < N_; j0 += 64) {
        __syncthreads();
        #pragma unroll
        for (int t = 0; t < 16; t++) {
            int e = tid + t * 256;
            int j = e & 63, d = e >> 6;
            Ks[j * 68 + d] = Kg[(size_t)d * N_ + j0 + j];
            Vs[d * 68 + j] = Vg[(size_t)d * N_ + j0 + j];
        }
        __syncthreads();

        // ---- S = Q K^T  (warp: 16 rows x 64 cols = 8 n-tiles) ----
        float s[8][4];
        #pragma unroll
        for (int jt = 0; jt < 8; jt++)
            #pragma unroll
            for (int r = 0; r < 4; r++) s[jt][r] = 0.0f;

        #pragma unroll
        for (int ks = 0; ks < 64; ks += 8) {
            uint32_t a0 = __float_as_uint(Qs[(m0 + g) * 68 + ks + tg]);
            uint32_t a1 = __float_as_uint(Qs[(m0 + 8 + g) * 68 + ks + tg]);
            uint32_t a2 = __float_as_uint(Qs[(m0 + g) * 68 + ks + tg + 4]);
            uint32_t a3 = __float_as_uint(Qs[(m0 + 8 + g) * 68 + ks + tg + 4]);
            #pragma unroll
            for (int jt = 0; jt < 8; jt++) {
                uint32_t b0 = __float_as_uint(Ks[(jt * 8 + g) * 68 + ks + tg]);
                uint32_t b1 = __float_as_uint(Ks[(jt * 8 + g) * 68 + ks + tg + 4]);
                mma_tf32(s[jt][0], s[jt][1], s[jt][2], s[jt][3],
                         a0, a1, a2, a3, b0, b1);
            }
        }

        // ---- bias + scale + online softmax ----
        float mxa = -1e30f, mxb = -1e30f;
        #pragma unroll
        for (int jt = 0; jt < 8; jt++) {
            #pragma unroll
            for (int p = 0; p < 2; p++) {
                int j = j0 + jt * 8 + 2 * tg + p;
                int j1 = j >> 5, j2 = j & 31;
                float ba = Rs[((i1a - j1) & 31) * 32 + ((i2a - j2) & 31)];
                float bb = Rs[((i1b - j1) & 31) * 32 + ((i2b - j2) & 31)];
                s[jt][p]     = (s[jt][p]     + ba) * 0.125f;
                s[jt][2 + p] = (s[jt][2 + p] + bb) * 0.125f;
                mxa = fmaxf(mxa, s[jt][p]);
                mxb = fmaxf(mxb, s[jt][2 + p]);
            }
        }
        mxa = fmaxf(mxa, __shfl_xor_sync(FULL, mxa, 1));
        mxa = fmaxf(mxa, __shfl_xor_sync(FULL, mxa, 2));
        mxb = fmaxf(mxb, __shfl_xor_sync(FULL, mxb, 1));
        mxb = fmaxf(mxb, __shfl_xor_sync(FULL, mxb, 2));

        float mnA = fmaxf(mA, mxa), mnB = fmaxf(mB, mxb);
        float fA = __expf(mA - mnA), fB = __expf(mB - mnB);
        mA = mnA; mB = mnB;

        float sa = 0.0f, sb = 0.0f;
        #pragma unroll
        for (int jt = 0; jt < 8; jt++) {
            #pragma unroll
            for (int p = 0; p < 2; p++) {
                float pa = __expf(s[jt][p] - mA);
                float pb = __expf(s[jt][2 + p] - mB);
                sa += pa; sb += pb;
                s[jt][p]     = to_tf32(pa);
                s[jt][2 + p] = to_tf32(pb);
            }
        }
        sa += __shfl_xor_sync(FULL, sa, 1);
        sa += __shfl_xor_sync(FULL, sa, 2);
        sb += __shfl_xor_sync(FULL, sb, 1);
        sb += __shfl_xor_sync(FULL, sb, 2);
        lA = lA * fA + sa;
        lB = lB * fB + sb;

        #pragma unroll
        for (int dt = 0; dt < 8; dt++) {
            o[dt][0] *= fA; o[dt][1] *= fA;
            o[dt][2] *= fB; o[dt][3] *= fB;
        }

        // ---- O += P V^T : P frag (C layout) -> A frag via shuffles ----
        int src0 = (lane & ~3) | (tg >> 1);
        int src2 = src0 + 2;
        bool odd = (tg & 1);
        #pragma unroll
        for (int jt = 0; jt < 8; jt++) {
            float t00 = __shfl_sync(FULL, s[jt][0], src0);
            float t10 = __shfl_sync(FULL, s[jt][1], src0);
            float t02 = __shfl_sync(FULL, s[jt][0], src2);
            float t12 = __shfl_sync(FULL, s[jt][1], src2);
            float t20 = __shfl_sync(FULL, s[jt][2], src0);
            float t30 = __shfl_sync(FULL, s[jt][3], src0);
            float t22 = __shfl_sync(FULL, s[jt][2], src2);
            float t32 = __shfl_sync(FULL, s[jt][3], src2);
            uint32_t a0 = __float_as_uint(odd ? t10 : t00);
            uint32_t a2 = __float_as_uint(odd ? t12 : t02);
            uint32_t a1 = __float_as_uint(odd ? t30 : t20);
            uint32_t a3 = __float_as_uint(odd ? t32 : t22);
            #pragma unroll
            for (int dt = 0; dt < 8; dt++) {
                uint32_t b0 = __float_as_uint(Vs[(dt * 8 + g) * 68 + jt * 8 + tg]);
                uint32_t b1 = __float_as_uint(Vs[(dt * 8 + g) * 68 + jt * 8 + tg + 4]);
                mma_tf32(o[dt][0], o[dt][1], o[dt][2], o[dt][3],
                         a0, a1, a2, a3, b0, b1);
            }
        }
    }

    // ---- epilogue: normalize, tf32-round, store [n][r] ----
    float invA = 1.0f / lA, invB = 1.0f / lB;
    float* ab = g_att + (size_t)b * N_ * HD_;
    #pragma unroll
    for (int dt = 0; dt < 8; dt++) {
        int col = h * DK_ + dt * 8 + 2 * tg;
        float2 va = make_float2(to_tf32(o[dt][0] * invA), to_tf32(o[dt][1] * invA));
        *(float2*)&ab[(size_t)i_a * HD_ + col] = va;
        float2 vb = make_float2(to_tf32(o[dt][2] * invB), to_tf32(o[dt][3] * invB));
        *(float2*)&ab[(size_t)i_b * HD_ + col] = vb;
    }
}

// ---------------------------------------------------------------------------
// Kernel C: out[b][c][n] = W0[c] . att[b][n] + x[b][c][n]
// Block tile 128(c) x 128(n), K=512 in 16 chunks of 32.
// ---------------------------------------------------------------------------
__global__ __launch_bounds__(256) void out_kernel(
    const float* __restrict__ W0,
    const float* __restrict__ x,
    float* __restrict__ out)
{
    int tid = threadIdx.x;
    int lane = tid & 31, w = tid >> 5;
    int g = lane >> 2, tg = lane & 3;
    int mw = w & 3, nw = w >> 2;
    int n0 = blockIdx.x * 128;
    int b  = blockIdx.y;

    __shared__ float W0s[128][36];  // [c][k]
    __shared__ float As[128][36];   // [n][k]

    const float* ab = g_att + (size_t)b * N_ * HD_;

    float acc[2][8][4];
    #pragma unroll
    for (int i = 0; i < 2; i++)
        #pragma unroll
        for (int j = 0; j < 8; j++)
            #pragma unroll
            for (int k = 0; k < 4; k++) acc[i][j][k] = 0.0f;

    for (int kc = 0; kc < 16; kc++) {
        __syncthreads();
        #pragma unroll
        for (int t = 0; t < 16; t++) {
            int e = tid + t * 256;
            int k = e & 31, m = e >> 5;
            W0s[m][k] = to_tf32(W0[m * HD_ + kc * 32 + k]);
        }
        #pragma unroll
        for (int t = 0; t < 16; t++) {
            int e = tid + t * 256;
            int k = e & 31, n = e >> 5;
            As[n][k] = ab[(size_t)(n0 + n) * HD_ + kc * 32 + k];
        }
        __syncthreads();

        #pragma unroll
        for (int ks = 0; ks < 32; ks += 8) {
            uint32_t a[2][4];
            #pragma unroll
            for (int mt = 0; mt < 2; mt++) {
                int row = mw * 32 + mt * 16;
                a[mt][0] = __float_as_uint(W0s[row + g][ks + tg]);
                a[mt][1] = __float_as_uint(W0s[row + 8 + g][ks + tg]);
                a[mt][2] = __float_as_uint(W0s[row + g][ks + tg + 4]);
                a[mt][3] = __float_as_uint(W0s[row + 8 + g][ks + tg + 4]);
            }
            #pragma unroll
            for (int nt = 0; nt < 8; nt++) {
                int col = nw * 64 + nt * 8 + g;
                uint32_t b0 = __float_as_uint(As[col][ks + tg]);
                uint32_t b1 = __float_as_uint(As[col][ks + tg + 4]);
                #pragma unroll
                for (int mt = 0; mt < 2; mt++)
                    mma_tf32(acc[mt][nt][0], acc[mt][nt][1], acc[mt][nt][2], acc[mt][nt][3],
                             a[mt][0], a[mt][1], a[mt][2], a[mt][3], b0, b1);
            }
        }
    }

    const float* xb = x + (size_t)b * C_ * N_;
    float* ob = out + (size_t)b * C_ * N_;
    #pragma unroll
    for (int mt = 0; mt < 2; mt++) {
        int row_a = mw * 32 + mt * 16 + g;
        #pragma unroll
        for (int nt = 0; nt < 8; nt++) {
            int col = n0 + nw * 64 + nt * 8 + 2 * tg;
            float2 xa = *(const float2*)&xb[(size_t)row_a * N_ + col];
            float2 va = make_float2(acc[mt][nt][0] + xa.x, acc[mt][nt][1] + xa.y);
            *(float2*)&ob[(size_t)row_a * N_ + col] = va;
            float2 xbv = *(const float2*)&xb[(size_t)(row_a + 8) * N_ + col];
            float2 vb = make_float2(acc[mt][nt][2] + xbv.x, acc[mt][nt][3] + xbv.y);
            *(float2*)&ob[(size_t)(row_a + 8) * N_ + col] = vb;
        }
    }
}

// ---------------------------------------------------------------------------
extern "C" void kernel_launch(void* const* d_in, const int* in_sizes, int n_in,
                              void* d_out, int out_size)
{
    const float* x  = (const float*)d_in[0];
    const float* Wq = (const float*)d_in[1];
    const float* Wk = (const float*)d_in[2];
    const float* Wv = (const float*)d_in[3];
    const float* R  = (const float*)d_in[4];
    const float* W0 = (const float*)d_in[5];
    float* out = (float*)d_out;

    const int ATTN_SMEM = (128 * 68 + 64 * 68 + 64 * 68 + 1024) * 4;  // 73728 B
    cudaFuncSetAttribute(attn_kernel, cudaFuncAttributeMaxDynamicSharedMemorySize, ATTN_SMEM);

    qkv_kernel<<<dim3(8, 12, 32), 256>>>(x, Wq, Wk, Wv);
    attn_kernel<<<dim3(8, 8, 32), 256, ATTN_SMEM>>>(R);
    out_kernel<<<dim3(8, 32), 256>>>(W0, x, out);
}

// round 3
// speedup vs baseline: 6.1105x; 2.0230x over previous
#include <cuda_runtime.h>
#include <cuda_bf16.h>
#include <cstdint>

#define B_   32
#define C_   128
#define N_   1024   // L*L
#define H_   8
#define DK_  64
#define HD_  512    // H*DK
#define R3_  1536   // 3*HD
#define FULL 0xffffffffu

// Scratch (allocation-free contract: __device__ globals), bf16, [n]-major
__device__ __nv_bfloat16 g_qkv[(size_t)B_ * N_ * R3_];  // [b][n][r] r:0..511 Q,512..1023 K,1024..1535 V
__device__ __nv_bfloat16 g_att[(size_t)B_ * N_ * HD_];  // [b][n][h*64+d]

__device__ __forceinline__ uint32_t smem_u32(const void* p) {
    return (uint32_t)__cvta_generic_to_shared(p);
}
// pack two f32 into bf16x2 register: lo -> bits[15:0], hi -> bits[31:16]
__device__ __forceinline__ uint32_t pack_bf16(float lo, float hi) {
    uint32_t r;
    asm("cvt.rn.bf16x2.f32 %0, %1, %2;" : "=r"(r) : "f"(hi), "f"(lo));
    return r;
}
__device__ __forceinline__ void ldsm4(uint32_t& r0, uint32_t& r1, uint32_t& r2, uint32_t& r3, uint32_t a) {
    asm volatile("ldmatrix.sync.aligned.m8n8.x4.shared.b16 {%0,%1,%2,%3},[%4];"
                 : "=r"(r0), "=r"(r1), "=r"(r2), "=r"(r3) : "r"(a));
}
__device__ __forceinline__ void ldsm4t(uint32_t& r0, uint32_t& r1, uint32_t& r2, uint32_t& r3, uint32_t a) {
    asm volatile("ldmatrix.sync.aligned.m8n8.x4.trans.shared.b16 {%0,%1,%2,%3},[%4];"
                 : "=r"(r0), "=r"(r1), "=r"(r2), "=r"(r3) : "r"(a));
}
__device__ __forceinline__ void mma_bf16(float* d, const uint32_t* a, uint32_t b0, uint32_t b1) {
    asm volatile("mma.sync.aligned.m16n8k16.row.col.f32.bf16.bf16.f32 "
                 "{%0,%1,%2,%3},{%4,%5,%6,%7},{%8,%9},{%0,%1,%2,%3};"
                 : "+f"(d[0]), "+f"(d[1]), "+f"(d[2]), "+f"(d[3])
                 : "r"(a[0]), "r"(a[1]), "r"(a[2]), "r"(a[3]), "r"(b0), "r"(b1));
}
__device__ __forceinline__ void cp16(void* s, const void* g) {
    asm volatile("cp.async.cg.shared.global [%0],[%1],16;" :: "r"(smem_u32(s)), "l"(g));
}

// ---------------------------------------------------------------------------
// Kernel A: QKV.  g_qkv[b][n][r] = bf16( X^T W^T ), X scaled by inv_layer.
// D[m=n][n'=r]: A = X^T (trans-ldmatrix on Xs[c][n]), B = W (ldmatrix on Ws[r][c])
// Block: 128(n) x 128(r), K=128 in 2 chunks of 64. Warps 4(m) x 2(n').
// ---------------------------------------------------------------------------
__global__ __launch_bounds__(256) void qkv_kernel(
    const float* __restrict__ x,
    const float* __restrict__ Wq,
    const float* __restrict__ Wk,
    const float* __restrict__ Wv)
{
    const float inv_layer = 0.44721359549995793f;  // 1/sqrt(5)
    int tid = threadIdx.x, lane = tid & 31, w = tid >> 5;
    int g = lane >> 2, tg = lane & 3;
    int mw = w & 3, nw = w >> 2;
    int n0 = blockIdx.x * 128, r0 = blockIdx.y * 128, b = blockIdx.z;

    const float* W = (r0 < HD_) ? Wq : (r0 < 2 * HD_) ? Wk : Wv;
    int rw0 = r0 & (HD_ - 1);
    const float* xb = x + (size_t)b * C_ * N_;

    __shared__ __align__(16) __nv_bfloat16 Xs[64 * 136];  // [c][n], stride 136 (272B ≡ 16 mod 128)
    __shared__ __align__(16) __nv_bfloat16 Ws[128 * 72];  // [r][c], stride 72 (144B ≡ 16 mod 128)

    float acc[2][8][4];
    #pragma unroll
    for (int i = 0; i < 2; i++)
        #pragma unroll
        for (int j = 0; j < 8; j++)
            #pragma unroll
            for (int k = 0; k < 4; k++) acc[i][j][k] = 0.0f;

    #pragma unroll
    for (int kc = 0; kc < 2; kc++) {
        __syncthreads();
        #pragma unroll
        for (int t = 0; t < 16; t++) {
            int e = tid + t * 256;
            int c = e >> 6, nn = (e & 63) * 2;
            float2 v = *(const float2*)&xb[(size_t)(kc * 64 + c) * N_ + n0 + nn];
            *(uint32_t*)&Xs[c * 136 + nn] = pack_bf16(v.x * inv_layer, v.y * inv_layer);
        }
        #pragma unroll
        for (int t = 0; t < 16; t++) {
            int e = tid + t * 256;
            int r = e >> 5, cc = (e & 31) * 2;
            float2 v = *(const float2*)&W[(size_t)(rw0 + r) * C_ + kc * 64 + cc];
            *(uint32_t*)&Ws[r * 72 + cc] = pack_bf16(v.x, v.y);
        }
        __syncthreads();

        #pragma unroll
        for (int ks = 0; ks < 64; ks += 16) {
            uint32_t a[2][4];
            #pragma unroll
            for (int mt = 0; mt < 2; mt++) {
                int row = ks + (lane & 7) + ((lane >> 4) << 3);          // c
                int col = mw * 32 + mt * 16 + ((lane >> 3) & 1) * 8;     // n
                ldsm4t(a[mt][0], a[mt][1], a[mt][2], a[mt][3], smem_u32(&Xs[row * 136 + col]));
            }
            #pragma unroll
            for (int ntp = 0; ntp < 4; ntp++) {
                uint32_t b0, b1, b2, b3;
                int row = nw * 64 + ntp * 16 + (lane & 7) + ((lane >> 4) << 3);  // r
                int col = ks + ((lane >> 3) & 1) * 8;                            // c
                ldsm4(b0, b1, b2, b3, smem_u32(&Ws[row * 72 + col]));
                #pragma unroll
                for (int mt = 0; mt < 2; mt++) {
                    mma_bf16(acc[mt][2 * ntp],     a[mt], b0, b1);
                    mma_bf16(acc[mt][2 * ntp + 1], a[mt], b2, b3);
                }
            }
        }
    }

    __nv_bfloat16* ob = g_qkv + (size_t)b * N_ * R3_;
    #pragma unroll
    for (int mt = 0; mt < 2; mt++) {
        int na = n0 + mw * 32 + mt * 16 + g;
        #pragma unroll
        for (int nt = 0; nt < 8; nt++) {
            int rc = r0 + nw * 64 + nt * 8 + 2 * tg;
            *(uint32_t*)&ob[(size_t)na * R3_ + rc]       = pack_bf16(acc[mt][nt][0], acc[mt][nt][1]);
            *(uint32_t*)&ob[(size_t)(na + 8) * R3_ + rc] = pack_bf16(acc[mt][nt][2], acc[mt][nt][3]);
        }
    }
}

// ---------------------------------------------------------------------------
// Kernel B: flash attention. Block = (128 queries, head, batch), 8 warps x 16 rows.
// bf16 mma, ldmatrix fragments, cp.async double-buffered K/V (j-step 64).
// ---------------------------------------------------------------------------
__global__ __launch_bounds__(256, 2) void attn_kernel(const float* __restrict__ R)
{
    extern __shared__ __align__(16) char smraw[];
    __nv_bfloat16* Qs = (__nv_bfloat16*)smraw;   // [128][72]
    __nv_bfloat16* Kb = Qs + 128 * 72;           // 2 x [64][72]
    __nv_bfloat16* Vb = Kb + 2 * 64 * 72;        // 2 x [64][72]
    float* Rs = (float*)(Vb + 2 * 64 * 72);      // [1024]

    int tid = threadIdx.x, lane = tid & 31, w = tid >> 5;
    int g = lane >> 2, tg = lane & 3;
    int i0 = blockIdx.x * 128, h = blockIdx.y, b = blockIdx.z;
    int m0 = w * 16;

    const __nv_bfloat16* qb = g_qkv + (size_t)b * N_ * R3_;
    const __nv_bfloat16* Qg = qb + h * DK_;
    const __nv_bfloat16* Kg = qb + HD_ + h * DK_;
    const __nv_bfloat16* Vg = qb + 2 * HD_ + h * DK_;

    // async: Q tile, bias table, K/V tile 0
    #pragma unroll
    for (int t = 0; t < 4; t++) {
        int e = tid + t * 256;
        int i = e >> 3, seg = e & 7;
        cp16(&Qs[i * 72 + seg * 8], Qg + (size_t)(i0 + i) * R3_ + seg * 8);
    }
    cp16(&Rs[tid * 4], R + h * 1024 + tid * 4);
    #pragma unroll
    for (int t = 0; t < 2; t++) {
        int e = tid + t * 256;
        int j = e >> 3, seg = e & 7;
        cp16(&Kb[j * 72 + seg * 8], Kg + (size_t)j * R3_ + seg * 8);
        cp16(&Vb[j * 72 + seg * 8], Vg + (size_t)j * R3_ + seg * 8);
    }
    asm volatile("cp.async.commit_group;");

    float o[8][4];
    #pragma unroll
    for (int dt = 0; dt < 8; dt++)
        #pragma unroll
        for (int r = 0; r < 4; r++) o[dt][r] = 0.0f;
    float mA = -1e30f, mB = -1e30f, lA = 0.0f, lB = 0.0f;

    int i_a = i0 + m0 + g, i_b = i_a + 8;
    int i1a = i_a >> 5, i2a = i_a & 31;
    int i1b = i_b >> 5, i2b = i_b & 31;

    for (int it = 0; it < 16; it++) {
        asm volatile("cp.async.wait_group 0;");
        __syncthreads();
        int cur = it & 1;
        if (it < 15) {
            int nb = cur ^ 1;
            int j0n = (it + 1) * 64;
            #pragma unroll
            for (int t = 0; t < 2; t++) {
                int e = tid + t * 256;
                int j = e >> 3, seg = e & 7;
                cp16(&Kb[nb * 64 * 72 + j * 72 + seg * 8], Kg + (size_t)(j0n + j) * R3_ + seg * 8);
                cp16(&Vb[nb * 64 * 72 + j * 72 + seg * 8], Vg + (size_t)(j0n + j) * R3_ + seg * 8);
            }
            asm volatile("cp.async.commit_group;");
        }
        const __nv_bfloat16* Ks = Kb + cur * 64 * 72;
        const __nv_bfloat16* Vs = Vb + cur * 64 * 72;
        int j0 = it * 64;

        // ---- S = Q K^T ----
        float s[8][4];
        #pragma unroll
        for (int jt = 0; jt < 8; jt++)
            #pragma unroll
            for (int r = 0; r < 4; r++) s[jt][r] = 0.0f;

        #pragma unroll
        for (int ks = 0; ks < 64; ks += 16) {
            uint32_t a[4];
            ldsm4(a[0], a[1], a[2], a[3],
                  smem_u32(&Qs[(m0 + (lane & 15)) * 72 + ks + (lane >> 4) * 8]));
            #pragma unroll
            for (int ntp = 0; ntp < 4; ntp++) {
                uint32_t b0, b1, b2, b3;
                int row = ntp * 16 + (lane & 7) + ((lane >> 4) << 3);   // j
                int col = ks + ((lane >> 3) & 1) * 8;                   // d
                ldsm4(b0, b1, b2, b3, smem_u32(&Ks[row * 72 + col]));
                mma_bf16(s[2 * ntp],     a, b0, b1);
                mma_bf16(s[2 * ntp + 1], a, b2, b3);
            }
        }

        // ---- bias + scale + online softmax ----
        float mxa = -1e30f, mxb = -1e30f;
        #pragma unroll
        for (int jt = 0; jt < 8; jt++) {
            #pragma unroll
            for (int p = 0; p < 2; p++) {
                int j = j0 + jt * 8 + 2 * tg + p;
                int j1 = j >> 5, j2 = j & 31;
                float ba = Rs[((i1a - j1) & 31) * 32 + ((i2a - j2) & 31)];
                float bb = Rs[((i1b - j1) & 31) * 32 + ((i2b - j2) & 31)];
                s[jt][p]     = (s[jt][p]     + ba) * 0.125f;
                s[jt][2 + p] = (s[jt][2 + p] + bb) * 0.125f;
                mxa = fmaxf(mxa, s[jt][p]);
                mxb = fmaxf(mxb, s[jt][2 + p]);
            }
        }
        mxa = fmaxf(mxa, __shfl_xor_sync(FULL, mxa, 1));
        mxa = fmaxf(mxa, __shfl_xor_sync(FULL, mxa, 2));
        mxb = fmaxf(mxb, __shfl_xor_sync(FULL, mxb, 1));
        mxb = fmaxf(mxb, __shfl_xor_sync(FULL, mxb, 2));

        float mnA = fmaxf(mA, mxa), mnB = fmaxf(mB, mxb);
        float fA = __expf(mA - mnA), fB = __expf(mB - mnB);
        mA = mnA; mB = mnB;

        float sa = 0.0f, sb = 0.0f;
        #pragma unroll
        for (int jt = 0; jt < 8; jt++) {
            #pragma unroll
            for (int p = 0; p < 2; p++) {
                float pa = __expf(s[jt][p] - mA);
                float pb = __expf(s[jt][2 + p] - mB);
                sa += pa; sb += pb;
                s[jt][p] = pa; s[jt][2 + p] = pb;
            }
        }
        sa += __shfl_xor_sync(FULL, sa, 1);
        sa += __shfl_xor_sync(FULL, sa, 2);
        sb += __shfl_xor_sync(FULL, sb, 1);
        sb += __shfl_xor_sync(FULL, sb, 2);
        lA = lA * fA + sa;
        lB = lB * fB + sb;

        #pragma unroll
        for (int dt = 0; dt < 8; dt++) {
            o[dt][0] *= fA; o[dt][1] *= fA;
            o[dt][2] *= fB; o[dt][3] *= fB;
        }

        // ---- O += P V : P C-frags pack directly into bf16 A-frags ----
        #pragma unroll
        for (int kq = 0; kq < 4; kq++) {
            uint32_t a[4];
            a[0] = pack_bf16(s[2 * kq][0],     s[2 * kq][1]);
            a[1] = pack_bf16(s[2 * kq][2],     s[2 * kq][3]);
            a[2] = pack_bf16(s[2 * kq + 1][0], s[2 * kq + 1][1]);
            a[3] = pack_bf16(s[2 * kq + 1][2], s[2 * kq + 1][3]);
            #pragma unroll
            for (int dtp = 0; dtp < 4; dtp++) {
                uint32_t b0, b1, b2, b3;
                int row = kq * 16 + (lane & 7) + ((lane >> 3) & 1) * 8;  // j
                int col = (2 * dtp + (lane >> 4)) * 8;                   // d
                ldsm4t(b0, b1, b2, b3, smem_u32(&Vs[row * 72 + col]));
                mma_bf16(o[2 * dtp],     a, b0, b1);
                mma_bf16(o[2 * dtp + 1], a, b2, b3);
            }
        }
    }

    // ---- epilogue ----
    float invA = 1.0f / lA, invB = 1.0f / lB;
    __nv_bfloat16* ab = g_att + (size_t)b * N_ * HD_;
    #pragma unroll
    for (int dt = 0; dt < 8; dt++) {
        int col = h * DK_ + dt * 8 + 2 * tg;
        *(uint32_t*)&ab[(size_t)i_a * HD_ + col] = pack_bf16(o[dt][0] * invA, o[dt][1] * invA);
        *(uint32_t*)&ab[(size_t)i_b * HD_ + col] = pack_bf16(o[dt][2] * invB, o[dt][3] * invB);
    }
}

// ---------------------------------------------------------------------------
// Kernel C: out[b][c][n] = W0[c] . att[b][n] + x[b][c][n]
// A = W0s[c][k] (ldmatrix), B = As[n][k] (ldmatrix). K=512 in 8 chunks of 64.
// ---------------------------------------------------------------------------
__global__ __launch_bounds__(256) void out_kernel(
    const float* __restrict__ W0,
    const float* __restrict__ x,
    float* __restrict__ out)
{
    int tid = threadIdx.x, lane = tid & 31, w = tid >> 5;
    int g = lane >> 2, tg = lane & 3;
    int mw = w & 3, nw = w >> 2;
    int n0 = blockIdx.x * 128, b = blockIdx.y;

    __shared__ __align__(16) __nv_bfloat16 W0s[128 * 72];  // [c][k]
    __shared__ __align__(16) __nv_bfloat16 As[128 * 72];   // [n][k]

    const __nv_bfloat16* ab = g_att + (size_t)b * N_ * HD_;

    float acc[2][8][4];
    #pragma unroll
    for (int i = 0; i < 2; i++)
        #pragma unroll
        for (int j = 0; j < 8; j++)
            #pragma unroll
            for (int k = 0; k < 4; k++) acc[i][j][k] = 0.0f;

    for (int kc = 0; kc < 8; kc++) {
        __syncthreads();
        #pragma unroll
        for (int t = 0; t < 16; t++) {
            int e = tid + t * 256;
            int m = e >> 5, cc = (e & 31) * 2;
            float2 v = *(const float2*)&W0[(size_t)m * HD_ + kc * 64 + cc];
            *(uint32_t*)&W0s[m * 72 + cc] = pack_bf16(v.x, v.y);
        }
        #pragma unroll
        for (int t = 0; t < 4; t++) {
            int e = tid + t * 256;
            int n = e >> 3, seg = e & 7;
            *(uint4*)&As[n * 72 + seg * 8] =
                *(const uint4*)&ab[(size_t)(n0 + n) * HD_ + kc * 64 + seg * 8];
        }
        __syncthreads();

        #pragma unroll
        for (int ks = 0; ks < 64; ks += 16) {
            uint32_t a[2][4];
            #pragma unroll
            for (int mt = 0; mt < 2; mt++) {
                int row = mw * 32 + mt * 16 + (lane & 15);
                int col = ks + (lane >> 4) * 8;
                ldsm4(a[mt][0], a[mt][1], a[mt][2], a[mt][3], smem_u32(&W0s[row * 72 + col]));
            }
            #pragma unroll
            for (int ntp = 0; ntp < 4; ntp++) {
                uint32_t b0, b1, b2, b3;
                int row = nw * 64 + ntp * 16 + (lane & 7) + ((lane >> 4) << 3);  // n
                int col = ks + ((lane >> 3) & 1) * 8;                            // k
                ldsm4(b0, b1, b2, b3, smem_u32(&As[row * 72 + col]));
                #pragma unroll
                for (int mt = 0; mt < 2; mt++) {
                    mma_bf16(acc[mt][2 * ntp],     a[mt], b0, b1);
                    mma_bf16(acc[mt][2 * ntp + 1], a[mt], b2, b3);
                }
            }
        }
    }

    const float* xb = x + (size_t)b * C_ * N_;
    float* ob = out + (size_t)b * C_ * N_;
    #pragma unroll
    for (int mt = 0; mt < 2; mt++) {
        int row_a = mw * 32 + mt * 16 + g;
        #pragma unroll
        for (int nt = 0; nt < 8; nt++) {
            int col = n0 + nw * 64 + nt * 8 + 2 * tg;
            float2 xa = *(const float2*)&xb[(size_t)row_a * N_ + col];
            float2 va = make_float2(acc[mt][nt][0] + xa.x, acc[mt][nt][1] + xa.y);
            *(float2*)&ob[(size_t)row_a * N_ + col] = va;
            float2 xbv = *(const float2*)&xb[(size_t)(row_a + 8) * N_ + col];
            float2 vb = make_float2(acc[mt][nt][2] + xbv.x, acc[mt][nt][3] + xbv.y);
            *(float2*)&ob[(size_t)(row_a + 8) * N_ + col] = vb;
        }
    }
}

// ---------------------------------------------------------------------------
extern "C" void kernel_launch(void* const* d_in, const int* in_sizes, int n_in,
                              void* d_out, int out_size)
{
    const float* x  = (const float*)d_in[0];
    const float* Wq = (const float*)d_in[1];
    const float* Wk = (const float*)d_in[2];
    const float* Wv = (const float*)d_in[3];
    const float* R  = (const float*)d_in[4];
    const float* W0 = (const float*)d_in[5];
    float* out = (float*)d_out;

    const int ATTN_SMEM = (128 * 72 + 4 * 64 * 72) * 2 + 1024 * 4;  // 59392 B
    cudaFuncSetAttribute(attn_kernel, cudaFuncAttributeMaxDynamicSharedMemorySize, ATTN_SMEM);

    qkv_kernel<<<dim3(8, 12, 32), 256>>>(x, Wq, Wk, Wv);
    attn_kernel<<<dim3(8, 8, 32), 256, ATTN_SMEM>>>(R);
    out_kernel<<<dim3(8, 32), 256>>>(W0, x, out);
}

// round 4
// speedup vs baseline: 8.1333x; 1.3310x over previous
#include <cuda_runtime.h>
#include <cuda_bf16.h>
#include <cstdint>

#define B_   32
#define C_   128
#define N_   1024   // L*L
#define H_   8
#define DK_  64
#define HD_  512    // H*DK
#define R3_  1536   // 3*HD
#define FULL 0xffffffffu

// 0.125 * log2(e): folded into Q (at QKV epilogue) and into bias table (at load)
#define QSC  0.1803368801111354f
#define INVL 0.44721359549995793f   // 1/sqrt(5)

// Scratch (allocation-free contract: __device__ globals)
__device__ __nv_bfloat16 g_xb [(size_t)B_ * C_ * N_];   // x * inv_layer, bf16
__device__ __nv_bfloat16 g_wb [(size_t)R3_ * C_];       // [Wq;Wk;Wv] bf16
__device__ __nv_bfloat16 g_w0b[(size_t)C_ * HD_];       // W0 bf16
__device__ __nv_bfloat16 g_qkv[(size_t)B_ * N_ * R3_];  // [b][n][r]; Q pre-scaled by QSC
__device__ __nv_bfloat16 g_att[(size_t)B_ * N_ * HD_];  // [b][n][h*64+d]

__device__ __forceinline__ uint32_t smem_u32(const void* p) {
    return (uint32_t)__cvta_generic_to_shared(p);
}
__device__ __forceinline__ uint32_t pack_bf16(float lo, float hi) {
    uint32_t r;
    asm("cvt.rn.bf16x2.f32 %0, %1, %2;" : "=r"(r) : "f"(hi), "f"(lo));
    return r;
}
__device__ __forceinline__ float ex2(float x) {
    float y; asm("ex2.approx.f32 %0, %1;" : "=f"(y) : "f"(x)); return y;
}
__device__ __forceinline__ void ldsm4(uint32_t& r0, uint32_t& r1, uint32_t& r2, uint32_t& r3, uint32_t a) {
    asm volatile("ldmatrix.sync.aligned.m8n8.x4.shared.b16 {%0,%1,%2,%3},[%4];"
                 : "=r"(r0), "=r"(r1), "=r"(r2), "=r"(r3) : "r"(a));
}
__device__ __forceinline__ void ldsm4t(uint32_t& r0, uint32_t& r1, uint32_t& r2, uint32_t& r3, uint32_t a) {
    asm volatile("ldmatrix.sync.aligned.m8n8.x4.trans.shared.b16 {%0,%1,%2,%3},[%4];"
                 : "=r"(r0), "=r"(r1), "=r"(r2), "=r"(r3) : "r"(a));
}
__device__ __forceinline__ void mma_bf16(float* d, const uint32_t* a, uint32_t b0, uint32_t b1) {
    asm volatile("mma.sync.aligned.m16n8k16.row.col.f32.bf16.bf16.f32 "
                 "{%0,%1,%2,%3},{%4,%5,%6,%7},{%8,%9},{%0,%1,%2,%3};"
                 : "+f"(d[0]), "+f"(d[1]), "+f"(d[2]), "+f"(d[3])
                 : "r"(a[0]), "r"(a[1]), "r"(a[2]), "r"(a[3]), "r"(b0), "r"(b1));
}
__device__ __forceinline__ void cp16(void* s, const void* g) {
    asm volatile("cp.async.cg.shared.global [%0],[%1],16;" :: "r"(smem_u32(s)), "l"(g));
}
__device__ __forceinline__ void cp_commit() { asm volatile("cp.async.commit_group;"); }
__device__ __forceinline__ void cp_wait0()  { asm volatile("cp.async.wait_group 0;"); }
__device__ __forceinline__ void cp_wait1()  { asm volatile("cp.async.wait_group 1;"); }

// ---------------------------------------------------------------------------
// Prep 1: x -> bf16 (scaled by inv_layer).  2048 blocks x 256, 8 elems/thread.
// ---------------------------------------------------------------------------
__global__ __launch_bounds__(256) void prep_x(const float* __restrict__ x)
{
    size_t e = ((size_t)blockIdx.x * 256 + threadIdx.x) * 8;
    float4 a = *(const float4*)(x + e);
    float4 b = *(const float4*)(x + e + 4);
    uint4 o;
    o.x = pack_bf16(a.x * INVL, a.y * INVL);
    o.y = pack_bf16(a.z * INVL, a.w * INVL);
    o.z = pack_bf16(b.x * INVL, b.y * INVL);
    o.w = pack_bf16(b.z * INVL, b.w * INVL);
    *(uint4*)&g_xb[e] = o;
}

// ---------------------------------------------------------------------------
// Prep 2: Wq/Wk/Wv -> g_wb, W0 -> g_w0b.  128 blocks x 256.
// ---------------------------------------------------------------------------
__global__ __launch_bounds__(256) void prep_w(
    const float* __restrict__ Wq, const float* __restrict__ Wk,
    const float* __restrict__ Wv, const float* __restrict__ W0)
{
    int idx = blockIdx.x * 256 + threadIdx.x;
    const float* src;
    __nv_bfloat16* dst;
    size_t e;
    if (idx < 24576) {                   // 1536*128/8
        e = (size_t)idx * 8;
        int r = (int)(e >> 7), c = (int)(e & 127);
        src = (r < HD_) ? Wq + (size_t)r * C_ + c
            : (r < 2 * HD_) ? Wk + (size_t)(r - HD_) * C_ + c
            : Wv + (size_t)(r - 2 * HD_) * C_ + c;
        dst = g_wb + e;
    } else {                             // W0: 128*512/8 = 8192 threads
        e = (size_t)(idx - 24576) * 8;
        src = W0 + e;
        dst = g_w0b + e;
    }
    float4 a = *(const float4*)src;
    float4 b = *(const float4*)(src + 4);
    uint4 o;
    o.x = pack_bf16(a.x, a.y);
    o.y = pack_bf16(a.z, a.w);
    o.z = pack_bf16(b.x, b.y);
    o.w = pack_bf16(b.z, b.w);
    *(uint4*)dst = o;
}

// ---------------------------------------------------------------------------
// Kernel A: QKV.  g_qkv[b][n][r] = (X^T W^T); Q rows scaled by QSC.
// 128(n) x 128(r) tile, K=128 as 2 cp.async-prefetched chunks of 64.
// ---------------------------------------------------------------------------
__global__ __launch_bounds__(256) void qkv_kernel()
{
    extern __shared__ __align__(16) char smq[];
    __nv_bfloat16* Xs = (__nv_bfloat16*)smq;     // 2 x [64][136]
    __nv_bfloat16* Ws = Xs + 2 * 64 * 136;       // 2 x [128][72]

    int tid = threadIdx.x, lane = tid & 31, w = tid >> 5;
    int g = lane >> 2, tg = lane & 3;
    int mw = w & 3, nw = w >> 2;
    int n0 = blockIdx.x * 128, r0 = blockIdx.y * 128, b = blockIdx.z;

    const __nv_bfloat16* xb = g_xb + (size_t)b * C_ * N_;
    const __nv_bfloat16* wb = g_wb + (size_t)r0 * C_;

    #pragma unroll
    for (int kc = 0; kc < 2; kc++) {
        #pragma unroll
        for (int t = 0; t < 4; t++) {
            int e = tid + t * 256;
            int c = e >> 4, seg = e & 15;
            cp16(&Xs[kc * 64 * 136 + c * 136 + seg * 8],
                 xb + (size_t)(kc * 64 + c) * N_ + n0 + seg * 8);
        }
        #pragma unroll
        for (int t = 0; t < 4; t++) {
            int e = tid + t * 256;
            int r = e >> 3, seg = e & 7;
            cp16(&Ws[kc * 128 * 72 + r * 72 + seg * 8],
                 wb + (size_t)r * C_ + kc * 64 + seg * 8);
        }
        cp_commit();
    }

    float acc[2][8][4];
    #pragma unroll
    for (int i = 0; i < 2; i++)
        #pragma unroll
        for (int j = 0; j < 8; j++)
            #pragma unroll
            for (int k = 0; k < 4; k++) acc[i][j][k] = 0.0f;

    #pragma unroll
    for (int kc = 0; kc < 2; kc++) {
        if (kc == 0) cp_wait1(); else cp_wait0();
        __syncthreads();
        const __nv_bfloat16* Xc = Xs + kc * 64 * 136;
        const __nv_bfloat16* Wc = Ws + kc * 128 * 72;

        #pragma unroll
        for (int ks = 0; ks < 64; ks += 16) {
            uint32_t a[2][4];
            #pragma unroll
            for (int mt = 0; mt < 2; mt++) {
                int row = ks + (lane & 7) + ((lane >> 4) << 3);       // c
                int col = mw * 32 + mt * 16 + ((lane >> 3) & 1) * 8;  // n
                ldsm4t(a[mt][0], a[mt][1], a[mt][2], a[mt][3], smem_u32(&Xc[row * 136 + col]));
            }
            #pragma unroll
            for (int ntp = 0; ntp < 4; ntp++) {
                uint32_t b0, b1, b2, b3;
                int row = nw * 64 + ntp * 16 + (lane & 7) + ((lane >> 4) << 3);  // r
                int col = ks + ((lane >> 3) & 1) * 8;                            // c
                ldsm4(b0, b1, b2, b3, smem_u32(&Wc[row * 72 + col]));
                #pragma unroll
                for (int mt = 0; mt < 2; mt++) {
                    mma_bf16(acc[mt][2 * ntp],     a[mt], b0, b1);
                    mma_bf16(acc[mt][2 * ntp + 1], a[mt], b2, b3);
                }
            }
        }
    }

    float qs = (r0 < HD_) ? QSC : 1.0f;   // fold softmax scale into Q
    __nv_bfloat16* ob = g_qkv + (size_t)b * N_ * R3_;
    #pragma unroll
    for (int mt = 0; mt < 2; mt++) {
        int na = n0 + mw * 32 + mt * 16 + g;
        #pragma unroll
        for (int nt = 0; nt < 8; nt++) {
            int rc = r0 + nw * 64 + nt * 8 + 2 * tg;
            *(uint32_t*)&ob[(size_t)na * R3_ + rc] =
                pack_bf16(acc[mt][nt][0] * qs, acc[mt][nt][1] * qs);
            *(uint32_t*)&ob[(size_t)(na + 8) * R3_ + rc] =
                pack_bf16(acc[mt][nt][2] * qs, acc[mt][nt][3] * qs);
        }
    }
}

// ---------------------------------------------------------------------------
// Kernel B: flash attention without running max (scores provably small).
// p = exp2(QK' + bias'), accumulate l per-thread, reduce once at the end.
// ---------------------------------------------------------------------------
__global__ __launch_bounds__(256, 2) void attn_kernel(const float* __restrict__ R)
{
    extern __shared__ __align__(16) char smraw[];
    __nv_bfloat16* Qs = (__nv_bfloat16*)smraw;   // [128][72]
    __nv_bfloat16* Kb = Qs + 128 * 72;           // 2 x [64][72]
    __nv_bfloat16* Vb = Kb + 2 * 64 * 72;        // 2 x [64][72]
    float* Rs = (float*)(Vb + 2 * 64 * 72);      // [32][32], pre-scaled

    int tid = threadIdx.x, lane = tid & 31, w = tid >> 5;
    int g = lane >> 2, tg = lane & 3;
    int i0 = blockIdx.x * 128, h = blockIdx.y, b = blockIdx.z;
    int m0 = w * 16;

    const __nv_bfloat16* qb = g_qkv + (size_t)b * N_ * R3_;
    const __nv_bfloat16* Qg = qb + h * DK_;
    const __nv_bfloat16* Kg = qb + HD_ + h * DK_;
    const __nv_bfloat16* Vg = qb + 2 * HD_ + h * DK_;

    // async: Q tile, K/V tile 0; bias table scaled on the fly
    #pragma unroll
    for (int t = 0; t < 4; t++) {
        int e = tid + t * 256;
        int i = e >> 3, seg = e & 7;
        cp16(&Qs[i * 72 + seg * 8], Qg + (size_t)(i0 + i) * R3_ + seg * 8);
    }
    #pragma unroll
    for (int t = 0; t < 2; t++) {
        int e = tid + t * 256;
        int j = e >> 3, seg = e & 7;
        cp16(&Kb[j * 72 + seg * 8], Kg + (size_t)j * R3_ + seg * 8);
        cp16(&Vb[j * 72 + seg * 8], Vg + (size_t)j * R3_ + seg * 8);
    }
    cp_commit();
    {
        float4 rv = ((const float4*)(R + h * 1024))[tid];
        float4 sv = make_float4(rv.x * QSC, rv.y * QSC, rv.z * QSC, rv.w * QSC);
        ((float4*)Rs)[tid] = sv;
    }

    float o[8][4];
    #pragma unroll
    for (int dt = 0; dt < 8; dt++)
        #pragma unroll
        for (int r = 0; r < 4; r++) o[dt][r] = 0.0f;
    float lA = 0.0f, lB = 0.0f;

    int i_a = i0 + m0 + g, i_b = i_a + 8;
    int i1a = i_a >> 5, i2a = i_a & 31;
    int i1b = i_b >> 5, i2b = i_b & 31;
    int dA = i2a - 2 * tg;   // col(k,p) = (dA - 8k - p) & 31
    int dB = i2b - 2 * tg;

    // preload Q fragments (fixed for all 16 iterations)
    cp_wait0();
    __syncthreads();
    uint32_t qf[4][4];
    #pragma unroll
    for (int ks4 = 0; ks4 < 4; ks4++)
        ldsm4(qf[ks4][0], qf[ks4][1], qf[ks4][2], qf[ks4][3],
              smem_u32(&Qs[(m0 + (lane & 15)) * 72 + ks4 * 16 + (lane >> 4) * 8]));

    for (int it = 0; it < 16; it++) {
        cp_wait0();
        __syncthreads();
        int cur = it & 1;
        if (it < 15) {
            int nb = cur ^ 1;
            int j0n = (it + 1) * 64;
            #pragma unroll
            for (int t = 0; t < 2; t++) {
                int e = tid + t * 256;
                int j = e >> 3, seg = e & 7;
                cp16(&Kb[nb * 64 * 72 + j * 72 + seg * 8], Kg + (size_t)(j0n + j) * R3_ + seg * 8);
                cp16(&Vb[nb * 64 * 72 + j * 72 + seg * 8], Vg + (size_t)(j0n + j) * R3_ + seg * 8);
            }
            cp_commit();
        }
        const __nv_bfloat16* Ks = Kb + cur * 64 * 72;
        const __nv_bfloat16* Vs = Vb + cur * 64 * 72;

        // ---- S = Q K^T ----
        float s[8][4];
        #pragma unroll
        for (int jt = 0; jt < 8; jt++)
            #pragma unroll
            for (int r = 0; r < 4; r++) s[jt][r] = 0.0f;

        #pragma unroll
        for (int ks4 = 0; ks4 < 4; ks4++) {
            #pragma unroll
            for (int ntp = 0; ntp < 4; ntp++) {
                uint32_t b0, b1, b2, b3;
                int row = ntp * 16 + (lane & 7) + ((lane >> 4) << 3);   // j
                int col = ks4 * 16 + ((lane >> 3) & 1) * 8;             // d
                ldsm4(b0, b1, b2, b3, smem_u32(&Ks[row * 72 + col]));
                mma_bf16(s[2 * ntp],     qf[ks4], b0, b1);
                mma_bf16(s[2 * ntp + 1], qf[ks4], b2, b3);
            }
        }

        // ---- bias + exp2 (no max subtraction; scores bounded) ----
        const float* RA0 = Rs + (((i1a - 2 * it)     & 31) << 5);
        const float* RA1 = Rs + (((i1a - 2 * it - 1) & 31) << 5);
        const float* RB0 = Rs + (((i1b - 2 * it)     & 31) << 5);
        const float* RB1 = Rs + (((i1b - 2 * it - 1) & 31) << 5);
        #pragma unroll
        for (int jt = 0; jt < 8; jt++) {
            const float* ra = (jt < 4) ? RA0 : RA1;
            const float* rb = (jt < 4) ? RB0 : RB1;
            int k8 = (jt & 3) * 8;
            #pragma unroll
            for (int p = 0; p < 2; p++) {
                float pa = ex2(s[jt][p]     + ra[(dA - k8 - p) & 31]);
                float pb = ex2(s[jt][2 + p] + rb[(dB - k8 - p) & 31]);
                lA += pa; lB += pb;
                s[jt][p] = pa; s[jt][2 + p] = pb;
            }
        }

        // ---- O += P V ----
        #pragma unroll
        for (int kq = 0; kq < 4; kq++) {
            uint32_t a[4];
            a[0] = pack_bf16(s[2 * kq][0],     s[2 * kq][1]);
            a[1] = pack_bf16(s[2 * kq][2],     s[2 * kq][3]);
            a[2] = pack_bf16(s[2 * kq + 1][0], s[2 * kq + 1][1]);
            a[3] = pack_bf16(s[2 * kq + 1][2], s[2 * kq + 1][3]);
            #pragma unroll
            for (int dtp = 0; dtp < 4; dtp++) {
                uint32_t b0, b1, b2, b3;
                int row = kq * 16 + (lane & 7) + ((lane >> 3) & 1) * 8;  // j
                int col = (2 * dtp + (lane >> 4)) * 8;                   // d
                ldsm4t(b0, b1, b2, b3, smem_u32(&Vs[row * 72 + col]));
                mma_bf16(o[2 * dtp],     a, b0, b1);
                mma_bf16(o[2 * dtp + 1], a, b2, b3);
            }
        }
    }

    // ---- reduce l across the 4 tg lanes, normalize, store ----
    lA += __shfl_xor_sync(FULL, lA, 1);
    lA += __shfl_xor_sync(FULL, lA, 2);
    lB += __shfl_xor_sync(FULL, lB, 1);
    lB += __shfl_xor_sync(FULL, lB, 2);
    float invA = 1.0f / lA, invB = 1.0f / lB;

    __nv_bfloat16* ab = g_att + (size_t)b * N_ * HD_;
    #pragma unroll
    for (int dt = 0; dt < 8; dt++) {
        int col = h * DK_ + dt * 8 + 2 * tg;
        *(uint32_t*)&ab[(size_t)i_a * HD_ + col] = pack_bf16(o[dt][0] * invA, o[dt][1] * invA);
        *(uint32_t*)&ab[(size_t)i_b * HD_ + col] = pack_bf16(o[dt][2] * invB, o[dt][3] * invB);
    }
}

// ---------------------------------------------------------------------------
// Kernel C: out[b][c][n] = W0[c] . att[b][n] + x[b][c][n]
// K=512 in 8 cp.async double-buffered chunks of 64.
// ---------------------------------------------------------------------------
__global__ __launch_bounds__(256) void out_kernel(
    const float* __restrict__ x,
    float* __restrict__ out)
{
    extern __shared__ __align__(16) char smo[];
    __nv_bfloat16* W0s = (__nv_bfloat16*)smo;    // 2 x [128][72]
    __nv_bfloat16* As  = W0s + 2 * 128 * 72;     // 2 x [128][72]

    int tid = threadIdx.x, lane = tid & 31, w = tid >> 5;
    int g = lane >> 2, tg = lane & 3;
    int mw = w & 3, nw = w >> 2;
    int n0 = blockIdx.x * 128, b = blockIdx.y;

    const __nv_bfloat16* ab = g_att + (size_t)b * N_ * HD_;

    // preload chunk 0
    #pragma unroll
    for (int t = 0; t < 4; t++) {
        int e = tid + t * 256;
        int r = e >> 3, seg = e & 7;
        cp16(&W0s[r * 72 + seg * 8], g_w0b + (size_t)r * HD_ + seg * 8);
        cp16(&As[r * 72 + seg * 8],  ab + (size_t)(n0 + r) * HD_ + seg * 8);
    }
    cp_commit();

    float acc[2][8][4];
    #pragma unroll
    for (int i = 0; i < 2; i++)
        #pragma unroll
        for (int j = 0; j < 8; j++)
            #pragma unroll
            for (int k = 0; k < 4; k++) acc[i][j][k] = 0.0f;

    for (int kc = 0; kc < 8; kc++) {
        cp_wait0();
        __syncthreads();
        int cur = kc & 1;
        if (kc < 7) {
            int nb = cur ^ 1;
            int k0n = (kc + 1) * 64;
            #pragma unroll
            for (int t = 0; t < 4; t++) {
                int e = tid + t * 256;
                int r = e >> 3, seg = e & 7;
                cp16(&W0s[nb * 128 * 72 + r * 72 + seg * 8],
                     g_w0b + (size_t)r * HD_ + k0n + seg * 8);
                cp16(&As[nb * 128 * 72 + r * 72 + seg * 8],
                     ab + (size_t)(n0 + r) * HD_ + k0n + seg * 8);
            }
            cp_commit();
        }
        const __nv_bfloat16* Wc = W0s + cur * 128 * 72;
        const __nv_bfloat16* Ac = As  + cur * 128 * 72;

        #pragma unroll
        for (int ks = 0; ks < 64; ks += 16) {
            uint32_t a[2][4];
            #pragma unroll
            for (int mt = 0; mt < 2; mt++) {
                int row = mw * 32 + mt * 16 + (lane & 15);
                int col = ks + (lane >> 4) * 8;
                ldsm4(a[mt][0], a[mt][1], a[mt][2], a[mt][3], smem_u32(&Wc[row * 72 + col]));
            }
            #pragma unroll
            for (int ntp = 0; ntp < 4; ntp++) {
                uint32_t b0, b1, b2, b3;
                int row = nw * 64 + ntp * 16 + (lane & 7) + ((lane >> 4) << 3);  // n
                int col = ks + ((lane >> 3) & 1) * 8;                            // k
                ldsm4(b0, b1, b2, b3, smem_u32(&Ac[row * 72 + col]));
                #pragma unroll
                for (int mt = 0; mt < 2; mt++) {
                    mma_bf16(acc[mt][2 * ntp],     a[mt], b0, b1);
                    mma_bf16(acc[mt][2 * ntp + 1], a[mt], b2, b3);
                }
            }
        }
    }

    const float* xb = x + (size_t)b * C_ * N_;
    float* ob = out + (size_t)b * C_ * N_;
    #pragma unroll
    for (int mt = 0; mt < 2; mt++) {
        int row_a = mw * 32 + mt * 16 + g;
        #pragma unroll
        for (int nt = 0; nt < 8; nt++) {
            int col = n0 + nw * 64 + nt * 8 + 2 * tg;
            float2 xa = *(const float2*)&xb[(size_t)row_a * N_ + col];
            float2 va = make_float2(acc[mt][nt][0] + xa.x, acc[mt][nt][1] + xa.y);
            *(float2*)&ob[(size_t)row_a * N_ + col] = va;
            float2 xbv = *(const float2*)&xb[(size_t)(row_a + 8) * N_ + col];
            float2 vb = make_float2(acc[mt][nt][2] + xbv.x, acc[mt][nt][3] + xbv.y);
            *(float2*)&ob[(size_t)(row_a + 8) * N_ + col] = vb;
        }
    }
}

// ---------------------------------------------------------------------------
extern "C" void kernel_launch(void* const* d_in, const int* in_sizes, int n_in,
                              void* d_out, int out_size)
{
    const float* x  = (const float*)d_in[0];
    const float* Wq = (const float*)d_in[1];
    const float* Wk = (const float*)d_in[2];
    const float* Wv = (const float*)d_in[3];
    const float* R  = (const float*)d_in[4];
    const float* W0 = (const float*)d_in[5];
    float* out = (float*)d_out;

    const int QKV_SMEM  = (2 * 64 * 136 + 2 * 128 * 72) * 2;            // 71680 B
    const int ATTN_SMEM = (128 * 72 + 4 * 64 * 72) * 2 + 1024 * 4;      // 59392 B
    const int OUT_SMEM  = (4 * 128 * 72) * 2;                           // 73728 B
    cudaFuncSetAttribute(qkv_kernel,  cudaFuncAttributeMaxDynamicSharedMemorySize, QKV_SMEM);
    cudaFuncSetAttribute(attn_kernel, cudaFuncAttributeMaxDynamicSharedMemorySize, ATTN_SMEM);
    cudaFuncSetAttribute(out_kernel,  cudaFuncAttributeMaxDynamicSharedMemorySize, OUT_SMEM);

    prep_x<<<2048, 256>>>(x);
    prep_w<<<128, 256>>>(Wq, Wk, Wv, W0);
    qkv_kernel<<<dim3(8, 12, 32), 256, QKV_SMEM>>>();
    attn_kernel<<<dim3(8, 8, 32), 256, ATTN_SMEM>>>(R);
    out_kernel<<<dim3(8, 32), 256, OUT_SMEM>>>(x, out);
}

// round 5
// speedup vs baseline: 8.3369x; 1.0250x over previous
#include <cuda_runtime.h>
#include <cuda_bf16.h>
#include <cstdint>

#define B_   32
#define C_   128
#define N_   1024   // L*L
#define H_   8
#define DK_  64
#define HD_  512    // H*DK
#define R3_  1536   // 3*HD
#define FULL 0xffffffffu

// 0.125 * log2(e): folded into Q (at QKV epilogue) and into bias table (at load)
#define QSC  0.1803368801111354f
#define INVL 0.44721359549995793f   // 1/sqrt(5)

// Scratch (allocation-free contract: __device__ globals)
__device__ __nv_bfloat16 g_xb [(size_t)B_ * C_ * N_];   // x * inv_layer, bf16
__device__ __nv_bfloat16 g_wb [(size_t)R3_ * C_];       // [Wq;Wk;Wv] bf16
__device__ __nv_bfloat16 g_w0b[(size_t)C_ * HD_];       // W0 bf16
__device__ __nv_bfloat16 g_qkv[(size_t)B_ * N_ * R3_];  // [b][n][r]; Q pre-scaled by QSC
__device__ __nv_bfloat16 g_att[(size_t)B_ * N_ * HD_];  // [b][n][h*64+d]

__device__ __forceinline__ uint32_t smem_u32(const void* p) {
    return (uint32_t)__cvta_generic_to_shared(p);
}
__device__ __forceinline__ uint32_t pack_bf16(float lo, float hi) {
    uint32_t r;
    asm("cvt.rn.bf16x2.f32 %0, %1, %2;" : "=r"(r) : "f"(hi), "f"(lo));
    return r;
}
__device__ __forceinline__ float ex2(float x) {
    float y; asm("ex2.approx.f32 %0, %1;" : "=f"(y) : "f"(x)); return y;
}
__device__ __forceinline__ void ldsm4(uint32_t& r0, uint32_t& r1, uint32_t& r2, uint32_t& r3, uint32_t a) {
    asm volatile("ldmatrix.sync.aligned.m8n8.x4.shared.b16 {%0,%1,%2,%3},[%4];"
                 : "=r"(r0), "=r"(r1), "=r"(r2), "=r"(r3) : "r"(a));
}
__device__ __forceinline__ void ldsm4t(uint32_t& r0, uint32_t& r1, uint32_t& r2, uint32_t& r3, uint32_t a) {
    asm volatile("ldmatrix.sync.aligned.m8n8.x4.trans.shared.b16 {%0,%1,%2,%3},[%4];"
                 : "=r"(r0), "=r"(r1), "=r"(r2), "=r"(r3) : "r"(a));
}
__device__ __forceinline__ void mma_bf16(float* d, const uint32_t* a, uint32_t b0, uint32_t b1) {
    asm volatile("mma.sync.aligned.m16n8k16.row.col.f32.bf16.bf16.f32 "
                 "{%0,%1,%2,%3},{%4,%5,%6,%7},{%8,%9},{%0,%1,%2,%3};"
                 : "+f"(d[0]), "+f"(d[1]), "+f"(d[2]), "+f"(d[3])
                 : "r"(a[0]), "r"(a[1]), "r"(a[2]), "r"(a[3]), "r"(b0), "r"(b1));
}
__device__ __forceinline__ void cp16(void* s, const void* g) {
    asm volatile("cp.async.cg.shared.global [%0],[%1],16;" :: "r"(smem_u32(s)), "l"(g));
}
__device__ __forceinline__ void cp_commit() { asm volatile("cp.async.commit_group;"); }
__device__ __forceinline__ void cp_wait0()  { asm volatile("cp.async.wait_group 0;"); }
__device__ __forceinline__ void cp_wait1()  { asm volatile("cp.async.wait_group 1;"); }

// ---------------------------------------------------------------------------
// Prep 1: x -> bf16 (scaled by inv_layer).  2048 blocks x 256, 8 elems/thread.
// ---------------------------------------------------------------------------
__global__ __launch_bounds__(256) void prep_x(const float* __restrict__ x)
{
    size_t e = ((size_t)blockIdx.x * 256 + threadIdx.x) * 8;
    float4 a = *(const float4*)(x + e);
    float4 b = *(const float4*)(x + e + 4);
    uint4 o;
    o.x = pack_bf16(a.x * INVL, a.y * INVL);
    o.y = pack_bf16(a.z * INVL, a.w * INVL);
    o.z = pack_bf16(b.x * INVL, b.y * INVL);
    o.w = pack_bf16(b.z * INVL, b.w * INVL);
    *(uint4*)&g_xb[e] = o;
}

// ---------------------------------------------------------------------------
// Prep 2: Wq/Wk/Wv -> g_wb, W0 -> g_w0b.  128 blocks x 256.
// ---------------------------------------------------------------------------
__global__ __launch_bounds__(256) void prep_w(
    const float* __restrict__ Wq, const float* __restrict__ Wk,
    const float* __restrict__ Wv, const float* __restrict__ W0)
{
    int idx = blockIdx.x * 256 + threadIdx.x;
    const float* src;
    __nv_bfloat16* dst;
    size_t e;
    if (idx < 24576) {                   // 1536*128/8
        e = (size_t)idx * 8;
        int r = (int)(e >> 7), c = (int)(e & 127);
        src = (r < HD_) ? Wq + (size_t)r * C_ + c
            : (r < 2 * HD_) ? Wk + (size_t)(r - HD_) * C_ + c
            : Wv + (size_t)(r - 2 * HD_) * C_ + c;
        dst = g_wb + e;
    } else {                             // W0: 128*512/8 = 8192 threads
        e = (size_t)(idx - 24576) * 8;
        src = W0 + e;
        dst = g_w0b + e;
    }
    float4 a = *(const float4*)src;
    float4 b = *(const float4*)(src + 4);
    uint4 o;
    o.x = pack_bf16(a.x, a.y);
    o.y = pack_bf16(a.z, a.w);
    o.z = pack_bf16(b.x, b.y);
    o.w = pack_bf16(b.z, b.w);
    *(uint4*)dst = o;
}

// ---------------------------------------------------------------------------
// Kernel A: QKV.  g_qkv[b][n][r] = (X^T W^T); Q rows scaled by QSC.
// 128(n) x 128(r) tile, K=128 as 2 cp.async-prefetched chunks of 64.
// ---------------------------------------------------------------------------
__global__ __launch_bounds__(256, 2) void qkv_kernel()
{
    extern __shared__ __align__(16) char smq[];
    __nv_bfloat16* Xs = (__nv_bfloat16*)smq;     // 2 x [64][136]
    __nv_bfloat16* Ws = Xs + 2 * 64 * 136;       // 2 x [128][72]

    int tid = threadIdx.x, lane = tid & 31, w = tid >> 5;
    int g = lane >> 2, tg = lane & 3;
    int mw = w & 3, nw = w >> 2;
    int n0 = blockIdx.x * 128, r0 = blockIdx.y * 128, b = blockIdx.z;

    const __nv_bfloat16* xb = g_xb + (size_t)b * C_ * N_;
    const __nv_bfloat16* wb = g_wb + (size_t)r0 * C_;

    #pragma unroll
    for (int kc = 0; kc < 2; kc++) {
        #pragma unroll
        for (int t = 0; t < 4; t++) {
            int e = tid + t * 256;
            int c = e >> 4, seg = e & 15;
            cp16(&Xs[kc * 64 * 136 + c * 136 + seg * 8],
                 xb + (size_t)(kc * 64 + c) * N_ + n0 + seg * 8);
        }
        #pragma unroll
        for (int t = 0; t < 4; t++) {
            int e = tid + t * 256;
            int r = e >> 3, seg = e & 7;
            cp16(&Ws[kc * 128 * 72 + r * 72 + seg * 8],
                 wb + (size_t)r * C_ + kc * 64 + seg * 8);
        }
        cp_commit();
    }

    float acc[2][8][4];
    #pragma unroll
    for (int i = 0; i < 2; i++)
        #pragma unroll
        for (int j = 0; j < 8; j++)
            #pragma unroll
            for (int k = 0; k < 4; k++) acc[i][j][k] = 0.0f;

    #pragma unroll
    for (int kc = 0; kc < 2; kc++) {
        if (kc == 0) cp_wait1(); else cp_wait0();
        __syncthreads();
        const __nv_bfloat16* Xc = Xs + kc * 64 * 136;
        const __nv_bfloat16* Wc = Ws + kc * 128 * 72;

        #pragma unroll
        for (int ks = 0; ks < 64; ks += 16) {
            uint32_t a[2][4];
            #pragma unroll
            for (int mt = 0; mt < 2; mt++) {
                int row = ks + (lane & 7) + ((lane >> 4) << 3);       // c
                int col = mw * 32 + mt * 16 + ((lane >> 3) & 1) * 8;  // n
                ldsm4t(a[mt][0], a[mt][1], a[mt][2], a[mt][3], smem_u32(&Xc[row * 136 + col]));
            }
            #pragma unroll
            for (int ntp = 0; ntp < 4; ntp++) {
                uint32_t b0, b1, b2, b3;
                int row = nw * 64 + ntp * 16 + (lane & 7) + ((lane >> 4) << 3);  // r
                int col = ks + ((lane >> 3) & 1) * 8;                            // c
                ldsm4(b0, b1, b2, b3, smem_u32(&Wc[row * 72 + col]));
                #pragma unroll
                for (int mt = 0; mt < 2; mt++) {
                    mma_bf16(acc[mt][2 * ntp],     a[mt], b0, b1);
                    mma_bf16(acc[mt][2 * ntp + 1], a[mt], b2, b3);
                }
            }
        }
    }

    float qs = (r0 < HD_) ? QSC : 1.0f;   // fold softmax scale into Q
    __nv_bfloat16* ob = g_qkv + (size_t)b * N_ * R3_;
    #pragma unroll
    for (int mt = 0; mt < 2; mt++) {
        int na = n0 + mw * 32 + mt * 16 + g;
        #pragma unroll
        for (int nt = 0; nt < 8; nt++) {
            int rc = r0 + nw * 64 + nt * 8 + 2 * tg;
            *(uint32_t*)&ob[(size_t)na * R3_ + rc] =
                pack_bf16(acc[mt][nt][0] * qs, acc[mt][nt][1] * qs);
            *(uint32_t*)&ob[(size_t)(na + 8) * R3_ + rc] =
                pack_bf16(acc[mt][nt][2] * qs, acc[mt][nt][3] * qs);
        }
    }
}

// ---------------------------------------------------------------------------
// Kernel B: flash attention without running max; bias preloaded into the S
// accumulators (mma adds QK^T on top); 3-stage cp.async K/V pipeline.
// ---------------------------------------------------------------------------
__global__ __launch_bounds__(256, 2) void attn_kernel(const float* __restrict__ R)
{
    extern __shared__ __align__(16) char smraw[];
    __nv_bfloat16* Qs = (__nv_bfloat16*)smraw;   // [128][72]
    __nv_bfloat16* Kb = Qs + 128 * 72;           // 3 x [64][72]
    __nv_bfloat16* Vb = Kb + 3 * 64 * 72;        // 3 x [64][72]
    float* Rs = (float*)(Vb + 3 * 64 * 72);      // [32][32], pre-scaled

    int tid = threadIdx.x, lane = tid & 31, w = tid >> 5;
    int g = lane >> 2, tg = lane & 3;
    int i0 = blockIdx.x * 128, h = blockIdx.y, b = blockIdx.z;
    int m0 = w * 16;

    const __nv_bfloat16* qb = g_qkv + (size_t)b * N_ * R3_;
    const __nv_bfloat16* Qg = qb + h * DK_;
    const __nv_bfloat16* Kg = qb + HD_ + h * DK_;
    const __nv_bfloat16* Vg = qb + 2 * HD_ + h * DK_;

    // group A: Q tile + K/V stage 0
    #pragma unroll
    for (int t = 0; t < 4; t++) {
        int e = tid + t * 256;
        int i = e >> 3, seg = e & 7;
        cp16(&Qs[i * 72 + seg * 8], Qg + (size_t)(i0 + i) * R3_ + seg * 8);
    }
    #pragma unroll
    for (int t = 0; t < 2; t++) {
        int e = tid + t * 256;
        int j = e >> 3, seg = e & 7;
        cp16(&Kb[j * 72 + seg * 8], Kg + (size_t)j * R3_ + seg * 8);
        cp16(&Vb[j * 72 + seg * 8], Vg + (size_t)j * R3_ + seg * 8);
    }
    cp_commit();
    // group B: K/V stage 1
    #pragma unroll
    for (int t = 0; t < 2; t++) {
        int e = tid + t * 256;
        int j = e >> 3, seg = e & 7;
        cp16(&Kb[64 * 72 + j * 72 + seg * 8], Kg + (size_t)(64 + j) * R3_ + seg * 8);
        cp16(&Vb[64 * 72 + j * 72 + seg * 8], Vg + (size_t)(64 + j) * R3_ + seg * 8);
    }
    cp_commit();
    {
        float4 rv = ((const float4*)(R + h * 1024))[tid];
        float4 sv = make_float4(rv.x * QSC, rv.y * QSC, rv.z * QSC, rv.w * QSC);
        ((float4*)Rs)[tid] = sv;
    }

    float o[8][4];
    #pragma unroll
    for (int dt = 0; dt < 8; dt++)
        #pragma unroll
        for (int r = 0; r < 4; r++) o[dt][r] = 0.0f;
    float lA = 0.0f, lB = 0.0f;

    int i_a = i0 + m0 + g, i_b = i_a + 8;
    int i1a = i_a >> 5, i2a = i_a & 31;
    int i1b = i_b >> 5, i2b = i_b & 31;
    int dA = i2a - 2 * tg;   // col(k,p) = (dA - 8k - p) & 31
    int dB = i2b - 2 * tg;

    // preload Q fragments (fixed for all 16 iterations); group A must be done
    cp_wait1();
    __syncthreads();
    uint32_t qf[4][4];
    #pragma unroll
    for (int ks4 = 0; ks4 < 4; ks4++)
        ldsm4(qf[ks4][0], qf[ks4][1], qf[ks4][2], qf[ks4][3],
              smem_u32(&Qs[(m0 + (lane & 15)) * 72 + ks4 * 16 + (lane >> 4) * 8]));

    for (int it = 0; it < 16; it++) {
        if (it == 15) cp_wait0(); else cp_wait1();
        __syncthreads();
        if (it < 14) {
            int st = (it + 2) % 3;
            int j0n = (it + 2) * 64;
            #pragma unroll
            for (int t = 0; t < 2; t++) {
                int e = tid + t * 256;
                int j = e >> 3, seg = e & 7;
                cp16(&Kb[st * 64 * 72 + j * 72 + seg * 8], Kg + (size_t)(j0n + j) * R3_ + seg * 8);
                cp16(&Vb[st * 64 * 72 + j * 72 + seg * 8], Vg + (size_t)(j0n + j) * R3_ + seg * 8);
            }
            cp_commit();
        }
        int cur = it % 3;
        const __nv_bfloat16* Ks = Kb + cur * 64 * 72;
        const __nv_bfloat16* Vs = Vb + cur * 64 * 72;

        // ---- init S accumulators from bias (mma adds QK^T on top) ----
        const float* RA0 = Rs + (((i1a - 2 * it)     & 31) << 5);
        const float* RA1 = Rs + (((i1a - 2 * it - 1) & 31) << 5);
        const float* RB0 = Rs + (((i1b - 2 * it)     & 31) << 5);
        const float* RB1 = Rs + (((i1b - 2 * it - 1) & 31) << 5);
        float s[8][4];
        #pragma unroll
        for (int jt = 0; jt < 8; jt++) {
            const float* ra = (jt < 4) ? RA0 : RA1;
            const float* rb = (jt < 4) ? RB0 : RB1;
            int k8 = (jt & 3) * 8;
            #pragma unroll
            for (int p = 0; p < 2; p++) {
                s[jt][p]     = ra[(dA - k8 - p) & 31];
                s[jt][2 + p] = rb[(dB - k8 - p) & 31];
            }
        }

        // ---- S += Q K^T ----
        #pragma unroll
        for (int ks4 = 0; ks4 < 4; ks4++) {
            #pragma unroll
            for (int ntp = 0; ntp < 4; ntp++) {
                uint32_t b0, b1, b2, b3;
                int row = ntp * 16 + (lane & 7) + ((lane >> 4) << 3);   // j
                int col = ks4 * 16 + ((lane >> 3) & 1) * 8;             // d
                ldsm4(b0, b1, b2, b3, smem_u32(&Ks[row * 72 + col]));
                mma_bf16(s[2 * ntp],     qf[ks4], b0, b1);
                mma_bf16(s[2 * ntp + 1], qf[ks4], b2, b3);
            }
        }

        // ---- exp2 + l accumulation ----
        #pragma unroll
        for (int jt = 0; jt < 8; jt++) {
            #pragma unroll
            for (int p = 0; p < 2; p++) {
                float pa = ex2(s[jt][p]);
                float pb = ex2(s[jt][2 + p]);
                lA += pa; lB += pb;
                s[jt][p] = pa; s[jt][2 + p] = pb;
            }
        }

        // ---- O += P V ----
        #pragma unroll
        for (int kq = 0; kq < 4; kq++) {
            uint32_t a[4];
            a[0] = pack_bf16(s[2 * kq][0],     s[2 * kq][1]);
            a[1] = pack_bf16(s[2 * kq][2],     s[2 * kq][3]);
            a[2] = pack_bf16(s[2 * kq + 1][0], s[2 * kq + 1][1]);
            a[3] = pack_bf16(s[2 * kq + 1][2], s[2 * kq + 1][3]);
            #pragma unroll
            for (int dtp = 0; dtp < 4; dtp++) {
                uint32_t b0, b1, b2, b3;
                int row = kq * 16 + (lane & 7) + ((lane >> 3) & 1) * 8;  // j
                int col = (2 * dtp + (lane >> 4)) * 8;                   // d
                ldsm4t(b0, b1, b2, b3, smem_u32(&Vs[row * 72 + col]));
                mma_bf16(o[2 * dtp],     a, b0, b1);
                mma_bf16(o[2 * dtp + 1], a, b2, b3);
            }
        }
    }

    // ---- reduce l across the 4 tg lanes, normalize, store ----
    lA += __shfl_xor_sync(FULL, lA, 1);
    lA += __shfl_xor_sync(FULL, lA, 2);
    lB += __shfl_xor_sync(FULL, lB, 1);
    lB += __shfl_xor_sync(FULL, lB, 2);
    float invA = 1.0f / lA, invB = 1.0f / lB;

    __nv_bfloat16* ab = g_att + (size_t)b * N_ * HD_;
    #pragma unroll
    for (int dt = 0; dt < 8; dt++) {
        int col = h * DK_ + dt * 8 + 2 * tg;
        *(uint32_t*)&ab[(size_t)i_a * HD_ + col] = pack_bf16(o[dt][0] * invA, o[dt][1] * invA);
        *(uint32_t*)&ab[(size_t)i_b * HD_ + col] = pack_bf16(o[dt][2] * invB, o[dt][3] * invB);
    }
}

// ---------------------------------------------------------------------------
// Kernel C: out[b][c][n] = W0[c] . att[b][n] + x[b][c][n]
// K=512 in 8 cp.async double-buffered chunks of 64.
// ---------------------------------------------------------------------------
__global__ __launch_bounds__(256, 2) void out_kernel(
    const float* __restrict__ x,
    float* __restrict__ out)
{
    extern __shared__ __align__(16) char smo[];
    __nv_bfloat16* W0s = (__nv_bfloat16*)smo;    // 2 x [128][72]
    __nv_bfloat16* As  = W0s + 2 * 128 * 72;     // 2 x [128][72]

    int tid = threadIdx.x, lane = tid & 31, w = tid >> 5;
    int g = lane >> 2, tg = lane & 3;
    int mw = w & 3, nw = w >> 2;
    int n0 = blockIdx.x * 128, b = blockIdx.y;

    const __nv_bfloat16* ab = g_att + (size_t)b * N_ * HD_;

    // preload chunk 0
    #pragma unroll
    for (int t = 0; t < 4; t++) {
        int e = tid + t * 256;
        int r = e >> 3, seg = e & 7;
        cp16(&W0s[r * 72 + seg * 8], g_w0b + (size_t)r * HD_ + seg * 8);
        cp16(&As[r * 72 + seg * 8],  ab + (size_t)(n0 + r) * HD_ + seg * 8);
    }
    cp_commit();

    float acc[2][8][4];
    #pragma unroll
    for (int i = 0; i < 2; i++)
        #pragma unroll
        for (int j = 0; j < 8; j++)
            #pragma unroll
            for (int k = 0; k < 4; k++) acc[i][j][k] = 0.0f;

    for (int kc = 0; kc < 8; kc++) {
        cp_wait0();
        __syncthreads();
        int cur = kc & 1;
        if (kc < 7) {
            int nb = cur ^ 1;
            int k0n = (kc + 1) * 64;
            #pragma unroll
            for (int t = 0; t < 4; t++) {
                int e = tid + t * 256;
                int r = e >> 3, seg = e & 7;
                cp16(&W0s[nb * 128 * 72 + r * 72 + seg * 8],
                     g_w0b + (size_t)r * HD_ + k0n + seg * 8);
                cp16(&As[nb * 128 * 72 + r * 72 + seg * 8],
                     ab + (size_t)(n0 + r) * HD_ + k0n + seg * 8);
            }
            cp_commit();
        }
        const __nv_bfloat16* Wc = W0s + cur * 128 * 72;
        const __nv_bfloat16* Ac = As  + cur * 128 * 72;

        #pragma unroll
        for (int ks = 0; ks < 64; ks += 16) {
            uint32_t a[2][4];
            #pragma unroll
            for (int mt = 0; mt < 2; mt++) {
                int row = mw * 32 + mt * 16 + (lane & 15);
                int col = ks + (lane >> 4) * 8;
                ldsm4(a[mt][0], a[mt][1], a[mt][2], a[mt][3], smem_u32(&Wc[row * 72 + col]));
            }
            #pragma unroll
            for (int ntp = 0; ntp < 4; ntp++) {
                uint32_t b0, b1, b2, b3;
                int row = nw * 64 + ntp * 16 + (lane & 7) + ((lane >> 4) << 3);  // n
                int col = ks + ((lane >> 3) & 1) * 8;                            // k
                ldsm4(b0, b1, b2, b3, smem_u32(&Ac[row * 72 + col]));
                #pragma unroll
                for (int mt = 0; mt < 2; mt++) {
                    mma_bf16(acc[mt][2 * ntp],     a[mt], b0, b1);
                    mma_bf16(acc[mt][2 * ntp + 1], a[mt], b2, b3);
                }
            }
        }
    }

    const float* xb = x + (size_t)b * C_ * N_;
    float* ob = out + (size_t)b * C_ * N_;
    #pragma unroll
    for (int mt = 0; mt < 2; mt++) {
        int row_a = mw * 32 + mt * 16 + g;
        #pragma unroll
        for (int nt = 0; nt < 8; nt++) {
            int col = n0 + nw * 64 + nt * 8 + 2 * tg;
            float2 xa = *(const float2*)&xb[(size_t)row_a * N_ + col];
            float2 va = make_float2(acc[mt][nt][0] + xa.x, acc[mt][nt][1] + xa.y);
            *(float2*)&ob[(size_t)row_a * N_ + col] = va;
            float2 xbv = *(const float2*)&xb[(size_t)(row_a + 8) * N_ + col];
            float2 vb = make_float2(acc[mt][nt][2] + xbv.x, acc[mt][nt][3] + xbv.y);
            *(float2*)&ob[(size_t)(row_a + 8) * N_ + col] = vb;
        }
    }
}

// ---------------------------------------------------------------------------
extern "C" void kernel_launch(void* const* d_in, const int* in_sizes, int n_in,
                              void* d_out, int out_size)
{
    const float* x  = (const float*)d_in[0];
    const float* Wq = (const float*)d_in[1];
    const float* Wk = (const float*)d_in[2];
    const float* Wv = (const float*)d_in[3];
    const float* R  = (const float*)d_in[4];
    const float* W0 = (const float*)d_in[5];
    float* out = (float*)d_out;

    const int QKV_SMEM  = (2 * 64 * 136 + 2 * 128 * 72) * 2;            // 71680 B
    const int ATTN_SMEM = (128 * 72 + 6 * 64 * 72) * 2 + 1024 * 4;      // 77824 B
    const int OUT_SMEM  = (4 * 128 * 72) * 2;                           // 73728 B
    cudaFuncSetAttribute(qkv_kernel,  cudaFuncAttributeMaxDynamicSharedMemorySize, QKV_SMEM);
    cudaFuncSetAttribute(attn_kernel, cudaFuncAttributeMaxDynamicSharedMemorySize, ATTN_SMEM);
    cudaFuncSetAttribute(out_kernel,  cudaFuncAttributeMaxDynamicSharedMemorySize, OUT_SMEM);

    prep_x<<<2048, 256>>>(x);
    prep_w<<<128, 256>>>(Wq, Wk, Wv, W0);
    qkv_kernel<<<dim3(8, 12, 32), 256, QKV_SMEM>>>();
    attn_kernel<<<dim3(8, 8, 32), 256, ATTN_SMEM>>>(R);
    out_kernel<<<dim3(8, 32), 256, OUT_SMEM>>>(x, out);
}

// round 6
// speedup vs baseline: 9.1021x; 1.0918x over previous
#include <cuda_runtime.h>
#include <cuda_bf16.h>
#include <cstdint>

#define B_   32
#define C_   128
#define N_   1024   // L*L
#define H_   8
#define DK_  64
#define HD_  512    // H*DK
#define R3_  1536   // 3*HD
#define FULL 0xffffffffu

// 0.125 * log2(e): folded into Q (at QKV epilogue) and into bias table (at load)
#define QSC  0.1803368801111354f
#define INVL 0.44721359549995793f   // 1/sqrt(5)
#define ONESB 0x3F803F80u           // bf16x2 (1.0, 1.0)

// Scratch (allocation-free contract: __device__ globals)
__device__ __nv_bfloat16 g_xb [(size_t)B_ * C_ * N_];   // x * inv_layer, bf16
__device__ __nv_bfloat16 g_wb [(size_t)R3_ * C_];       // [Wq;Wk;Wv] bf16
__device__ __nv_bfloat16 g_w0b[(size_t)C_ * HD_];       // W0 bf16
__device__ __nv_bfloat16 g_qkv[(size_t)B_ * N_ * R3_];  // [b][n][r]; Q pre-scaled by QSC
__device__ __nv_bfloat16 g_att[(size_t)B_ * N_ * HD_];  // [b][n][h*64+d]

__device__ __forceinline__ uint32_t smem_u32(const void* p) {
    return (uint32_t)__cvta_generic_to_shared(p);
}
__device__ __forceinline__ uint32_t pack_bf16(float lo, float hi) {
    uint32_t r;
    asm("cvt.rn.bf16x2.f32 %0, %1, %2;" : "=r"(r) : "f"(hi), "f"(lo));
    return r;
}
__device__ __forceinline__ uint32_t ex2_bf16x2(uint32_t x) {
    uint32_t y;
    asm("ex2.approx.ftz.bf16x2 %0, %1;" : "=r"(y) : "r"(x));
    return y;
}
__device__ __forceinline__ void ldsm4(uint32_t& r0, uint32_t& r1, uint32_t& r2, uint32_t& r3, uint32_t a) {
    asm volatile("ldmatrix.sync.aligned.m8n8.x4.shared.b16 {%0,%1,%2,%3},[%4];"
                 : "=r"(r0), "=r"(r1), "=r"(r2), "=r"(r3) : "r"(a));
}
__device__ __forceinline__ void ldsm4t(uint32_t& r0, uint32_t& r1, uint32_t& r2, uint32_t& r3, uint32_t a) {
    asm volatile("ldmatrix.sync.aligned.m8n8.x4.trans.shared.b16 {%0,%1,%2,%3},[%4];"
                 : "=r"(r0), "=r"(r1), "=r"(r2), "=r"(r3) : "r"(a));
}
__device__ __forceinline__ void mma_bf16(float* d, const uint32_t* a, uint32_t b0, uint32_t b1) {
    asm volatile("mma.sync.aligned.m16n8k16.row.col.f32.bf16.bf16.f32 "
                 "{%0,%1,%2,%3},{%4,%5,%6,%7},{%8,%9},{%0,%1,%2,%3};"
                 : "+f"(d[0]), "+f"(d[1]), "+f"(d[2]), "+f"(d[3])
                 : "r"(a[0]), "r"(a[1]), "r"(a[2]), "r"(a[3]), "r"(b0), "r"(b1));
}
__device__ __forceinline__ void cp16(void* s, const void* g) {
    asm volatile("cp.async.cg.shared.global [%0],[%1],16;" :: "r"(smem_u32(s)), "l"(g));
}
__device__ __forceinline__ void cp_commit() { asm volatile("cp.async.commit_group;"); }
__device__ __forceinline__ void cp_wait0()  { asm volatile("cp.async.wait_group 0;"); }
__device__ __forceinline__ void cp_wait1()  { asm volatile("cp.async.wait_group 1;"); }

// ---------------------------------------------------------------------------
// Prep 1: x -> bf16 (scaled by inv_layer).  2048 blocks x 256, 8 elems/thread.
// ---------------------------------------------------------------------------
__global__ __launch_bounds__(256) void prep_x(const float* __restrict__ x)
{
    size_t e = ((size_t)blockIdx.x * 256 + threadIdx.x) * 8;
    float4 a = *(const float4*)(x + e);
    float4 b = *(const float4*)(x + e + 4);
    uint4 o;
    o.x = pack_bf16(a.x * INVL, a.y * INVL);
    o.y = pack_bf16(a.z * INVL, a.w * INVL);
    o.z = pack_bf16(b.x * INVL, b.y * INVL);
    o.w = pack_bf16(b.z * INVL, b.w * INVL);
    *(uint4*)&g_xb[e] = o;
}

// ---------------------------------------------------------------------------
// Prep 2: Wq/Wk/Wv -> g_wb, W0 -> g_w0b.  128 blocks x 256.
// ---------------------------------------------------------------------------
__global__ __launch_bounds__(256) void prep_w(
    const float* __restrict__ Wq, const float* __restrict__ Wk,
    const float* __restrict__ Wv, const float* __restrict__ W0)
{
    int idx = blockIdx.x * 256 + threadIdx.x;
    const float* src;
    __nv_bfloat16* dst;
    size_t e;
    if (idx < 24576) {                   // 1536*128/8
        e = (size_t)idx * 8;
        int r = (int)(e >> 7), c = (int)(e & 127);
        src = (r < HD_) ? Wq + (size_t)r * C_ + c
            : (r < 2 * HD_) ? Wk + (size_t)(r - HD_) * C_ + c
            : Wv + (size_t)(r - 2 * HD_) * C_ + c;
        dst = g_wb + e;
    } else {                             // W0: 128*512/8 = 8192 threads
        e = (size_t)(idx - 24576) * 8;
        src = W0 + e;
        dst = g_w0b + e;
    }
    float4 a = *(const float4*)src;
    float4 b = *(const float4*)(src + 4);
    uint4 o;
    o.x = pack_bf16(a.x, a.y);
    o.y = pack_bf16(a.z, a.w);
    o.z = pack_bf16(b.x, b.y);
    o.w = pack_bf16(b.z, b.w);
    *(uint4*)dst = o;
}

// ---------------------------------------------------------------------------
// Kernel A: QKV.  g_qkv[b][n][r] = (X^T W^T); Q rows scaled by QSC.
// ---------------------------------------------------------------------------
__global__ __launch_bounds__(256, 2) void qkv_kernel()
{
    extern __shared__ __align__(16) char smq[];
    __nv_bfloat16* Xs = (__nv_bfloat16*)smq;     // 2 x [64][136]
    __nv_bfloat16* Ws = Xs + 2 * 64 * 136;       // 2 x [128][72]

    int tid = threadIdx.x, lane = tid & 31, w = tid >> 5;
    int g = lane >> 2, tg = lane & 3;
    int mw = w & 3, nw = w >> 2;
    int n0 = blockIdx.x * 128, r0 = blockIdx.y * 128, b = blockIdx.z;

    const __nv_bfloat16* xb = g_xb + (size_t)b * C_ * N_;
    const __nv_bfloat16* wb = g_wb + (size_t)r0 * C_;

    #pragma unroll
    for (int kc = 0; kc < 2; kc++) {
        #pragma unroll
        for (int t = 0; t < 4; t++) {
            int e = tid + t * 256;
            int c = e >> 4, seg = e & 15;
            cp16(&Xs[kc * 64 * 136 + c * 136 + seg * 8],
                 xb + (size_t)(kc * 64 + c) * N_ + n0 + seg * 8);
        }
        #pragma unroll
        for (int t = 0; t < 4; t++) {
            int e = tid + t * 256;
            int r = e >> 3, seg = e & 7;
            cp16(&Ws[kc * 128 * 72 + r * 72 + seg * 8],
                 wb + (size_t)r * C_ + kc * 64 + seg * 8);
        }
        cp_commit();
    }

    float acc[2][8][4];
    #pragma unroll
    for (int i = 0; i < 2; i++)
        #pragma unroll
        for (int j = 0; j < 8; j++)
            #pragma unroll
            for (int k = 0; k < 4; k++) acc[i][j][k] = 0.0f;

    #pragma unroll
    for (int kc = 0; kc < 2; kc++) {
        if (kc == 0) cp_wait1(); else cp_wait0();
        __syncthreads();
        const __nv_bfloat16* Xc = Xs + kc * 64 * 136;
        const __nv_bfloat16* Wc = Ws + kc * 128 * 72;

        #pragma unroll
        for (int ks = 0; ks < 64; ks += 16) {
            uint32_t a[2][4];
            #pragma unroll
            for (int mt = 0; mt < 2; mt++) {
                int row = ks + (lane & 7) + ((lane >> 4) << 3);       // c
                int col = mw * 32 + mt * 16 + ((lane >> 3) & 1) * 8;  // n
                ldsm4t(a[mt][0], a[mt][1], a[mt][2], a[mt][3], smem_u32(&Xc[row * 136 + col]));
            }
            #pragma unroll
            for (int ntp = 0; ntp < 4; ntp++) {
                uint32_t b0, b1, b2, b3;
                int row = nw * 64 + ntp * 16 + (lane & 7) + ((lane >> 4) << 3);  // r
                int col = ks + ((lane >> 3) & 1) * 8;                            // c
                ldsm4(b0, b1, b2, b3, smem_u32(&Wc[row * 72 + col]));
                #pragma unroll
                for (int mt = 0; mt < 2; mt++) {
                    mma_bf16(acc[mt][2 * ntp],     a[mt], b0, b1);
                    mma_bf16(acc[mt][2 * ntp + 1], a[mt], b2, b3);
                }
            }
        }
    }

    float qs = (r0 < HD_) ? QSC : 1.0f;   // fold softmax scale into Q
    __nv_bfloat16* ob = g_qkv + (size_t)b * N_ * R3_;
    #pragma unroll
    for (int mt = 0; mt < 2; mt++) {
        int na = n0 + mw * 32 + mt * 16 + g;
        #pragma unroll
        for (int nt = 0; nt < 8; nt++) {
            int rc = r0 + nw * 64 + nt * 8 + 2 * tg;
            *(uint32_t*)&ob[(size_t)na * R3_ + rc] =
                pack_bf16(acc[mt][nt][0] * qs, acc[mt][nt][1] * qs);
            *(uint32_t*)&ob[(size_t)(na + 8) * R3_ + rc] =
                pack_bf16(acc[mt][nt][2] * qs, acc[mt][nt][3] * qs);
        }
    }
}

// ---------------------------------------------------------------------------
// Kernel B: flash attention. Bias preloaded into S accumulators; exp via
// bf16x2 MUFU (halved); l accumulated by an all-ones tensor-core mma.
// ---------------------------------------------------------------------------
__global__ __launch_bounds__(256, 2) void attn_kernel(const float* __restrict__ R)
{
    extern __shared__ __align__(16) char smraw[];
    __nv_bfloat16* Qs = (__nv_bfloat16*)smraw;   // [128][72]
    __nv_bfloat16* Kb = Qs + 128 * 72;           // 3 x [64][72]
    __nv_bfloat16* Vb = Kb + 3 * 64 * 72;        // 3 x [64][72]
    float2* Rp = (float2*)(Vb + 3 * 64 * 72);    // [32][32] pairs (c, c-1), pre-scaled

    int tid = threadIdx.x, lane = tid & 31, w = tid >> 5;
    int g = lane >> 2, tg = lane & 3;
    int i0 = blockIdx.x * 128, h = blockIdx.y, b = blockIdx.z;
    int m0 = w * 16;

    const __nv_bfloat16* qb = g_qkv + (size_t)b * N_ * R3_;
    const __nv_bfloat16* Qg = qb + h * DK_;
    const __nv_bfloat16* Kg = qb + HD_ + h * DK_;
    const __nv_bfloat16* Vg = qb + 2 * HD_ + h * DK_;

    // group A: Q tile + K/V stage 0
    #pragma unroll
    for (int t = 0; t < 4; t++) {
        int e = tid + t * 256;
        int i = e >> 3, seg = e & 7;
        cp16(&Qs[i * 72 + seg * 8], Qg + (size_t)(i0 + i) * R3_ + seg * 8);
    }
    #pragma unroll
    for (int t = 0; t < 2; t++) {
        int e = tid + t * 256;
        int j = e >> 3, seg = e & 7;
        cp16(&Kb[j * 72 + seg * 8], Kg + (size_t)j * R3_ + seg * 8);
        cp16(&Vb[j * 72 + seg * 8], Vg + (size_t)j * R3_ + seg * 8);
    }
    cp_commit();
    // group B: K/V stage 1
    #pragma unroll
    for (int t = 0; t < 2; t++) {
        int e = tid + t * 256;
        int j = e >> 3, seg = e & 7;
        cp16(&Kb[64 * 72 + j * 72 + seg * 8], Kg + (size_t)(64 + j) * R3_ + seg * 8);
        cp16(&Vb[64 * 72 + j * 72 + seg * 8], Vg + (size_t)(64 + j) * R3_ + seg * 8);
    }
    cp_commit();
    // bias table as (c, c-1) float2 pairs, scaled by QSC
    #pragma unroll
    for (int t = 0; t < 4; t++) {
        int idx = tid + t * 256;
        int r = idx >> 5, c = idx & 31;
        const float* Rr = R + h * 1024 + r * 32;
        Rp[idx] = make_float2(Rr[c] * QSC, Rr[(c - 1) & 31] * QSC);
    }

    float o[8][4];
    #pragma unroll
    for (int dt = 0; dt < 8; dt++)
        #pragma unroll
        for (int r = 0; r < 4; r++) o[dt][r] = 0.0f;
    float lacc[4] = {0.0f, 0.0f, 0.0f, 0.0f};   // ones-mma accumulator: c0=lA, c2=lB

    int i_a = i0 + m0 + g, i_b = i_a + 8;
    int i1a = i_a >> 5, i2a = i_a & 31;
    int i1b = i_b >> 5, i2b = i_b & 31;
    int dA = i2a - 2 * tg;   // pair col(k) = (dA - 8k) & 31
    int dB = i2b - 2 * tg;

    // preload Q fragments (fixed for all 16 iterations); group A must be done
    cp_wait1();
    __syncthreads();
    uint32_t qf[4][4];
    #pragma unroll
    for (int ks4 = 0; ks4 < 4; ks4++)
        ldsm4(qf[ks4][0], qf[ks4][1], qf[ks4][2], qf[ks4][3],
              smem_u32(&Qs[(m0 + (lane & 15)) * 72 + ks4 * 16 + (lane >> 4) * 8]));

    for (int it = 0; it < 16; it++) {
        if (it == 15) cp_wait0(); else cp_wait1();
        __syncthreads();
        if (it < 14) {
            int st = (it + 2) % 3;
            int j0n = (it + 2) * 64;
            #pragma unroll
            for (int t = 0; t < 2; t++) {
                int e = tid + t * 256;
                int j = e >> 3, seg = e & 7;
                cp16(&Kb[st * 64 * 72 + j * 72 + seg * 8], Kg + (size_t)(j0n + j) * R3_ + seg * 8);
                cp16(&Vb[st * 64 * 72 + j * 72 + seg * 8], Vg + (size_t)(j0n + j) * R3_ + seg * 8);
            }
            cp_commit();
        }
        int cur = it % 3;
        const __nv_bfloat16* Ks = Kb + cur * 64 * 72;
        const __nv_bfloat16* Vs = Vb + cur * 64 * 72;

        // ---- init S accumulators from bias (float2 pair loads) ----
        const float2* RA0 = Rp + (((i1a - 2 * it)     & 31) << 5);
        const float2* RA1 = Rp + (((i1a - 2 * it - 1) & 31) << 5);
        const float2* RB0 = Rp + (((i1b - 2 * it)     & 31) << 5);
        const float2* RB1 = Rp + (((i1b - 2 * it - 1) & 31) << 5);
        float s[8][4];
        #pragma unroll
        for (int jt = 0; jt < 8; jt++) {
            const float2* ra = (jt < 4) ? RA0 : RA1;
            const float2* rb = (jt < 4) ? RB0 : RB1;
            int k8 = (jt & 3) * 8;
            float2 va = ra[(dA - k8) & 31];
            float2 vb = rb[(dB - k8) & 31];
            s[jt][0] = va.x; s[jt][1] = va.y;
            s[jt][2] = vb.x; s[jt][3] = vb.y;
        }

        // ---- S += Q K^T ----
        #pragma unroll
        for (int ks4 = 0; ks4 < 4; ks4++) {
            #pragma unroll
            for (int ntp = 0; ntp < 4; ntp++) {
                uint32_t b0, b1, b2, b3;
                int row = ntp * 16 + (lane & 7) + ((lane >> 4) << 3);   // j
                int col = ks4 * 16 + ((lane >> 3) & 1) * 8;             // d
                ldsm4(b0, b1, b2, b3, smem_u32(&Ks[row * 72 + col]));
                mma_bf16(s[2 * ntp],     qf[ks4], b0, b1);
                mma_bf16(s[2 * ntp + 1], qf[ks4], b2, b3);
            }
        }

        // ---- pack -> bf16x2 exp2 -> A-fragments; l via ones-mma; O += P V ----
        #pragma unroll
        for (int kq = 0; kq < 4; kq++) {
            uint32_t a[4];
            a[0] = ex2_bf16x2(pack_bf16(s[2 * kq][0],     s[2 * kq][1]));
            a[1] = ex2_bf16x2(pack_bf16(s[2 * kq][2],     s[2 * kq][3]));
            a[2] = ex2_bf16x2(pack_bf16(s[2 * kq + 1][0], s[2 * kq + 1][1]));
            a[3] = ex2_bf16x2(pack_bf16(s[2 * kq + 1][2], s[2 * kq + 1][3]));
            mma_bf16(lacc, a, ONESB, ONESB);   // row sums -> l
            #pragma unroll
            for (int dtp = 0; dtp < 4; dtp++) {
                uint32_t b0, b1, b2, b3;
                int row = kq * 16 + (lane & 7) + ((lane >> 3) & 1) * 8;  // j
                int col = (2 * dtp + (lane >> 4)) * 8;                   // d
                ldsm4t(b0, b1, b2, b3, smem_u32(&Vs[row * 72 + col]));
                mma_bf16(o[2 * dtp],     a, b0, b1);
                mma_bf16(o[2 * dtp + 1], a, b2, b3);
            }
        }
    }

    // ---- normalize and store (every lane holds lA/lB directly) ----
    float invA = 1.0f / lacc[0], invB = 1.0f / lacc[2];
    __nv_bfloat16* ab = g_att + (size_t)b * N_ * HD_;
    #pragma unroll
    for (int dt = 0; dt < 8; dt++) {
        int col = h * DK_ + dt * 8 + 2 * tg;
        *(uint32_t*)&ab[(size_t)i_a * HD_ + col] = pack_bf16(o[dt][0] * invA, o[dt][1] * invA);
        *(uint32_t*)&ab[(size_t)i_b * HD_ + col] = pack_bf16(o[dt][2] * invB, o[dt][3] * invB);
    }
}

// ---------------------------------------------------------------------------
// Kernel C: out[b][c][n] = W0[c] . att[b][n] + x[b][c][n]
// ---------------------------------------------------------------------------
__global__ __launch_bounds__(256, 2) void out_kernel(
    const float* __restrict__ x,
    float* __restrict__ out)
{
    extern __shared__ __align__(16) char smo[];
    __nv_bfloat16* W0s = (__nv_bfloat16*)smo;    // 2 x [128][72]
    __nv_bfloat16* As  = W0s + 2 * 128 * 72;     // 2 x [128][72]

    int tid = threadIdx.x, lane = tid & 31, w = tid >> 5;
    int g = lane >> 2, tg = lane & 3;
    int mw = w & 3, nw = w >> 2;
    int n0 = blockIdx.x * 128, b = blockIdx.y;

    const __nv_bfloat16* ab = g_att + (size_t)b * N_ * HD_;

    #pragma unroll
    for (int t = 0; t < 4; t++) {
        int e = tid + t * 256;
        int r = e >> 3, seg = e & 7;
        cp16(&W0s[r * 72 + seg * 8], g_w0b + (size_t)r * HD_ + seg * 8);
        cp16(&As[r * 72 + seg * 8],  ab + (size_t)(n0 + r) * HD_ + seg * 8);
    }
    cp_commit();

    float acc[2][8][4];
    #pragma unroll
    for (int i = 0; i < 2; i++)
        #pragma unroll
        for (int j = 0; j < 8; j++)
            #pragma unroll
            for (int k = 0; k < 4; k++) acc[i][j][k] = 0.0f;

    for (int kc = 0; kc < 8; kc++) {
        cp_wait0();
        __syncthreads();
        int cur = kc & 1;
        if (kc < 7) {
            int nb = cur ^ 1;
            int k0n = (kc + 1) * 64;
            #pragma unroll
            for (int t = 0; t < 4; t++) {
                int e = tid + t * 256;
                int r = e >> 3, seg = e & 7;
                cp16(&W0s[nb * 128 * 72 + r * 72 + seg * 8],
                     g_w0b + (size_t)r * HD_ + k0n + seg * 8);
                cp16(&As[nb * 128 * 72 + r * 72 + seg * 8],
                     ab + (size_t)(n0 + r) * HD_ + k0n + seg * 8);
            }
            cp_commit();
        }
        const __nv_bfloat16* Wc = W0s + cur * 128 * 72;
        const __nv_bfloat16* Ac = As  + cur * 128 * 72;

        #pragma unroll
        for (int ks = 0; ks < 64; ks += 16) {
            uint32_t a[2][4];
            #pragma unroll
            for (int mt = 0; mt < 2; mt++) {
                int row = mw * 32 + mt * 16 + (lane & 15);
                int col = ks + (lane >> 4) * 8;
                ldsm4(a[mt][0], a[mt][1], a[mt][2], a[mt][3], smem_u32(&Wc[row * 72 + col]));
            }
            #pragma unroll
            for (int ntp = 0; ntp < 4; ntp++) {
                uint32_t b0, b1, b2, b3;
                int row = nw * 64 + ntp * 16 + (lane & 7) + ((lane >> 4) << 3);  // n
                int col = ks + ((lane >> 3) & 1) * 8;                            // k
                ldsm4(b0, b1, b2, b3, smem_u32(&Ac[row * 72 + col]));
                #pragma unroll
                for (int mt = 0; mt < 2; mt++) {
                    mma_bf16(acc[mt][2 * ntp],     a[mt], b0, b1);
                    mma_bf16(acc[mt][2 * ntp + 1], a[mt], b2, b3);
                }
            }
        }
    }

    const float* xb = x + (size_t)b * C_ * N_;
    float* ob = out + (size_t)b * C_ * N_;
    #pragma unroll
    for (int mt = 0; mt < 2; mt++) {
        int row_a = mw * 32 + mt * 16 + g;
        #pragma unroll
        for (int nt = 0; nt < 8; nt++) {
            int col = n0 + nw * 64 + nt * 8 + 2 * tg;
            float2 xa = *(const float2*)&xb[(size_t)row_a * N_ + col];
            float2 va = make_float2(acc[mt][nt][0] + xa.x, acc[mt][nt][1] + xa.y);
            *(float2*)&ob[(size_t)row_a * N_ + col] = va;
            float2 xbv = *(const float2*)&xb[(size_t)(row_a + 8) * N_ + col];
            float2 vb = make_float2(acc[mt][nt][2] + xbv.x, acc[mt][nt][3] + xbv.y);
            *(float2*)&ob[(size_t)(row_a + 8) * N_ + col] = vb;
        }
    }
}

// ---------------------------------------------------------------------------
extern "C" void kernel_launch(void* const* d_in, const int* in_sizes, int n_in,
                              void* d_out, int out_size)
{
    const float* x  = (const float*)d_in[0];
    const float* Wq = (const float*)d_in[1];
    const float* Wk = (const float*)d_in[2];
    const float* Wv = (const float*)d_in[3];
    const float* R  = (const float*)d_in[4];
    const float* W0 = (const float*)d_in[5];
    float* out = (float*)d_out;

    const int QKV_SMEM  = (2 * 64 * 136 + 2 * 128 * 72) * 2;            // 71680 B
    const int ATTN_SMEM = (128 * 72 + 6 * 64 * 72) * 2 + 32 * 32 * 8;   // 81920 B
    const int OUT_SMEM  = (4 * 128 * 72) * 2;                           // 73728 B
    cudaFuncSetAttribute(qkv_kernel,  cudaFuncAttributeMaxDynamicSharedMemorySize, QKV_SMEM);
    cudaFuncSetAttribute(attn_kernel, cudaFuncAttributeMaxDynamicSharedMemorySize, ATTN_SMEM);
    cudaFuncSetAttribute(out_kernel,  cudaFuncAttributeMaxDynamicSharedMemorySize, OUT_SMEM);

    prep_x<<<2048, 256>>>(x);
    prep_w<<<128, 256>>>(Wq, Wk, Wv, W0);
    qkv_kernel<<<dim3(8, 12, 32), 256, QKV_SMEM>>>();
    attn_kernel<<<dim3(8, 8, 32), 256, ATTN_SMEM>>>(R);
    out_kernel<<<dim3(8, 32), 256, OUT_SMEM>>>(x, out);
}

// round 7
// speedup vs baseline: 9.7177x; 1.0676x over previous
#include <cuda_runtime.h>
#include <cuda_bf16.h>
#include <cstdint>

#define B_   32
#define C_   128
#define N_   1024   // L*L
#define H_   8
#define DK_  64
#define HD_  512    // H*DK
#define R3_  1536   // 3*HD
#define FULL 0xffffffffu

// 0.125 * log2(e): folded into Q (at QKV epilogue) and into bias table (at load)
#define QSC  0.1803368801111354f
#define INVL 0.44721359549995793f   // 1/sqrt(5)
#define ONESB 0x3F803F80u           // bf16x2 (1.0, 1.0)

// Scratch (allocation-free contract: __device__ globals)
__device__ __nv_bfloat16 g_xb [(size_t)B_ * C_ * N_];   // x * inv_layer, bf16
__device__ __nv_bfloat16 g_wb [(size_t)R3_ * C_];       // [Wq;Wk;Wv] bf16
__device__ __nv_bfloat16 g_w0b[(size_t)C_ * HD_];       // W0 bf16
__device__ __nv_bfloat16 g_qkv[(size_t)B_ * N_ * R3_];  // [b][n][r]; Q pre-scaled by QSC
__device__ __nv_bfloat16 g_att[(size_t)B_ * N_ * HD_];  // [b][n][h*64+d]

__device__ __forceinline__ uint32_t smem_u32(const void* p) {
    return (uint32_t)__cvta_generic_to_shared(p);
}
__device__ __forceinline__ uint32_t pack_bf16(float lo, float hi) {
    uint32_t r;
    asm("cvt.rn.bf16x2.f32 %0, %1, %2;" : "=r"(r) : "f"(hi), "f"(lo));
    return r;
}
__device__ __forceinline__ uint32_t ex2_bf16x2(uint32_t x) {
    uint32_t y;
    asm("ex2.approx.ftz.bf16x2 %0, %1;" : "=r"(y) : "r"(x));
    return y;
}
__device__ __forceinline__ void ldsm4(uint32_t& r0, uint32_t& r1, uint32_t& r2, uint32_t& r3, uint32_t a) {
    asm volatile("ldmatrix.sync.aligned.m8n8.x4.shared.b16 {%0,%1,%2,%3},[%4];"
                 : "=r"(r0), "=r"(r1), "=r"(r2), "=r"(r3) : "r"(a));
}
__device__ __forceinline__ void ldsm4t(uint32_t& r0, uint32_t& r1, uint32_t& r2, uint32_t& r3, uint32_t a) {
    asm volatile("ldmatrix.sync.aligned.m8n8.x4.trans.shared.b16 {%0,%1,%2,%3},[%4];"
                 : "=r"(r0), "=r"(r1), "=r"(r2), "=r"(r3) : "r"(a));
}
__device__ __forceinline__ void mma_bf16(float* d, const uint32_t* a, uint32_t b0, uint32_t b1) {
    asm volatile("mma.sync.aligned.m16n8k16.row.col.f32.bf16.bf16.f32 "
                 "{%0,%1,%2,%3},{%4,%5,%6,%7},{%8,%9},{%0,%1,%2,%3};"
                 : "+f"(d[0]), "+f"(d[1]), "+f"(d[2]), "+f"(d[3])
                 : "r"(a[0]), "r"(a[1]), "r"(a[2]), "r"(a[3]), "r"(b0), "r"(b1));
}
__device__ __forceinline__ void cp16(void* s, const void* g) {
    asm volatile("cp.async.cg.shared.global [%0],[%1],16;" :: "r"(smem_u32(s)), "l"(g));
}
__device__ __forceinline__ void cp_commit() { asm volatile("cp.async.commit_group;"); }
__device__ __forceinline__ void cp_wait0()  { asm volatile("cp.async.wait_group 0;"); }
__device__ __forceinline__ void cp_wait1()  { asm volatile("cp.async.wait_group 1;"); }

// ---------------------------------------------------------------------------
// Prep 1: x -> bf16 (scaled by inv_layer).
// ---------------------------------------------------------------------------
__global__ __launch_bounds__(256) void prep_x(const float* __restrict__ x)
{
    size_t e = ((size_t)blockIdx.x * 256 + threadIdx.x) * 8;
    float4 a = *(const float4*)(x + e);
    float4 b = *(const float4*)(x + e + 4);
    uint4 o;
    o.x = pack_bf16(a.x * INVL, a.y * INVL);
    o.y = pack_bf16(a.z * INVL, a.w * INVL);
    o.z = pack_bf16(b.x * INVL, b.y * INVL);
    o.w = pack_bf16(b.z * INVL, b.w * INVL);
    *(uint4*)&g_xb[e] = o;
}

// ---------------------------------------------------------------------------
// Prep 2: Wq/Wk/Wv -> g_wb, W0 -> g_w0b.
// ---------------------------------------------------------------------------
__global__ __launch_bounds__(256) void prep_w(
    const float* __restrict__ Wq, const float* __restrict__ Wk,
    const float* __restrict__ Wv, const float* __restrict__ W0)
{
    int idx = blockIdx.x * 256 + threadIdx.x;
    const float* src;
    __nv_bfloat16* dst;
    size_t e;
    if (idx < 24576) {
        e = (size_t)idx * 8;
        int r = (int)(e >> 7), c = (int)(e & 127);
        src = (r < HD_) ? Wq + (size_t)r * C_ + c
            : (r < 2 * HD_) ? Wk + (size_t)(r - HD_) * C_ + c
            : Wv + (size_t)(r - 2 * HD_) * C_ + c;
        dst = g_wb + e;
    } else {
        e = (size_t)(idx - 24576) * 8;
        src = W0 + e;
        dst = g_w0b + e;
    }
    float4 a = *(const float4*)src;
    float4 b = *(const float4*)(src + 4);
    uint4 o;
    o.x = pack_bf16(a.x, a.y);
    o.y = pack_bf16(a.z, a.w);
    o.z = pack_bf16(b.x, b.y);
    o.w = pack_bf16(b.z, b.w);
    *(uint4*)dst = o;
}

// ---------------------------------------------------------------------------
// Kernel A: QKV.  g_qkv[b][n][r] = (X^T W^T); Q rows scaled by QSC.
// ---------------------------------------------------------------------------
__global__ __launch_bounds__(256, 2) void qkv_kernel()
{
    extern __shared__ __align__(16) char smq[];
    __nv_bfloat16* Xs = (__nv_bfloat16*)smq;     // 2 x [64][136]
    __nv_bfloat16* Ws = Xs + 2 * 64 * 136;       // 2 x [128][72]

    int tid = threadIdx.x, lane = tid & 31, w = tid >> 5;
    int g = lane >> 2, tg = lane & 3;
    int mw = w & 3, nw = w >> 2;
    int n0 = blockIdx.x * 128, r0 = blockIdx.y * 128, b = blockIdx.z;

    const __nv_bfloat16* xb = g_xb + (size_t)b * C_ * N_;
    const __nv_bfloat16* wb = g_wb + (size_t)r0 * C_;

    #pragma unroll
    for (int kc = 0; kc < 2; kc++) {
        #pragma unroll
        for (int t = 0; t < 4; t++) {
            int e = tid + t * 256;
            int c = e >> 4, seg = e & 15;
            cp16(&Xs[kc * 64 * 136 + c * 136 + seg * 8],
                 xb + (size_t)(kc * 64 + c) * N_ + n0 + seg * 8);
        }
        #pragma unroll
        for (int t = 0; t < 4; t++) {
            int e = tid + t * 256;
            int r = e >> 3, seg = e & 7;
            cp16(&Ws[kc * 128 * 72 + r * 72 + seg * 8],
                 wb + (size_t)r * C_ + kc * 64 + seg * 8);
        }
        cp_commit();
    }

    float acc[2][8][4];
    #pragma unroll
    for (int i = 0; i < 2; i++)
        #pragma unroll
        for (int j = 0; j < 8; j++)
            #pragma unroll
            for (int k = 0; k < 4; k++) acc[i][j][k] = 0.0f;

    #pragma unroll
    for (int kc = 0; kc < 2; kc++) {
        if (kc == 0) cp_wait1(); else cp_wait0();
        __syncthreads();
        const __nv_bfloat16* Xc = Xs + kc * 64 * 136;
        const __nv_bfloat16* Wc = Ws + kc * 128 * 72;

        #pragma unroll
        for (int ks = 0; ks < 64; ks += 16) {
            uint32_t a[2][4];
            #pragma unroll
            for (int mt = 0; mt < 2; mt++) {
                int row = ks + (lane & 7) + ((lane >> 4) << 3);       // c
                int col = mw * 32 + mt * 16 + ((lane >> 3) & 1) * 8;  // n
                ldsm4t(a[mt][0], a[mt][1], a[mt][2], a[mt][3], smem_u32(&Xc[row * 136 + col]));
            }
            #pragma unroll
            for (int ntp = 0; ntp < 4; ntp++) {
                uint32_t b0, b1, b2, b3;
                int row = nw * 64 + ntp * 16 + (lane & 7) + ((lane >> 4) << 3);  // r
                int col = ks + ((lane >> 3) & 1) * 8;                            // c
                ldsm4(b0, b1, b2, b3, smem_u32(&Wc[row * 72 + col]));
                #pragma unroll
                for (int mt = 0; mt < 2; mt++) {
                    mma_bf16(acc[mt][2 * ntp],     a[mt], b0, b1);
                    mma_bf16(acc[mt][2 * ntp + 1], a[mt], b2, b3);
                }
            }
        }
    }

    float qs = (r0 < HD_) ? QSC : 1.0f;   // fold softmax scale into Q
    __nv_bfloat16* ob = g_qkv + (size_t)b * N_ * R3_;
    #pragma unroll
    for (int mt = 0; mt < 2; mt++) {
        int na = n0 + mw * 32 + mt * 16 + g;
        #pragma unroll
        for (int nt = 0; nt < 8; nt++) {
            int rc = r0 + nw * 64 + nt * 8 + 2 * tg;
            *(uint32_t*)&ob[(size_t)na * R3_ + rc] =
                pack_bf16(acc[mt][nt][0] * qs, acc[mt][nt][1] * qs);
            *(uint32_t*)&ob[(size_t)(na + 8) * R3_ + rc] =
                pack_bf16(acc[mt][nt][2] * qs, acc[mt][nt][3] * qs);
        }
    }
}

// ---------------------------------------------------------------------------
// Kernel B: flash attention. 4 warps x 32 query rows: each K/V ldmatrix now
// feeds 2 m16 tiles (halved shared-pipe traffic per query). Bias preloaded
// into S accumulators; bf16x2 exp; l via ones-mma.
// ---------------------------------------------------------------------------
__global__ __launch_bounds__(128, 2) void attn_kernel(const float* __restrict__ R)
{
    extern __shared__ __align__(16) char smraw[];
    __nv_bfloat16* Qs = (__nv_bfloat16*)smraw;   // [128][72]
    __nv_bfloat16* Kb = Qs + 128 * 72;           // 3 x [64][72]
    __nv_bfloat16* Vb = Kb + 3 * 64 * 72;        // 3 x [64][72]
    float2* Rp = (float2*)(Vb + 3 * 64 * 72);    // [32][32] pairs (c, c-1), pre-scaled

    int tid = threadIdx.x, lane = tid & 31, w = tid >> 5;
    int g = lane >> 2, tg = lane & 3;
    int i0 = blockIdx.x * 128, h = blockIdx.y, b = blockIdx.z;
    int m0 = w * 32;

    const __nv_bfloat16* qb = g_qkv + (size_t)b * N_ * R3_;
    const __nv_bfloat16* Qg = qb + h * DK_;
    const __nv_bfloat16* Kg = qb + HD_ + h * DK_;
    const __nv_bfloat16* Vg = qb + 2 * HD_ + h * DK_;

    // group A: Q tile + K/V stage 0
    #pragma unroll
    for (int t = 0; t < 8; t++) {
        int e = tid + t * 128;
        int i = e >> 3, seg = e & 7;
        cp16(&Qs[i * 72 + seg * 8], Qg + (size_t)(i0 + i) * R3_ + seg * 8);
    }
    #pragma unroll
    for (int t = 0; t < 4; t++) {
        int e = tid + t * 128;
        int j = e >> 3, seg = e & 7;
        cp16(&Kb[j * 72 + seg * 8], Kg + (size_t)j * R3_ + seg * 8);
        cp16(&Vb[j * 72 + seg * 8], Vg + (size_t)j * R3_ + seg * 8);
    }
    cp_commit();
    // group B: K/V stage 1
    #pragma unroll
    for (int t = 0; t < 4; t++) {
        int e = tid + t * 128;
        int j = e >> 3, seg = e & 7;
        cp16(&Kb[64 * 72 + j * 72 + seg * 8], Kg + (size_t)(64 + j) * R3_ + seg * 8);
        cp16(&Vb[64 * 72 + j * 72 + seg * 8], Vg + (size_t)(64 + j) * R3_ + seg * 8);
    }
    cp_commit();
    // bias table as (c, c-1) float2 pairs, scaled by QSC
    #pragma unroll
    for (int t = 0; t < 8; t++) {
        int idx = tid + t * 128;
        int r = idx >> 5, c = idx & 31;
        const float* Rr = R + h * 1024 + r * 32;
        Rp[idx] = make_float2(Rr[c] * QSC, Rr[(c - 1) & 31] * QSC);
    }

    float o[2][8][4];
    #pragma unroll
    for (int mh = 0; mh < 2; mh++)
        #pragma unroll
        for (int dt = 0; dt < 8; dt++)
            #pragma unroll
            for (int r = 0; r < 4; r++) o[mh][dt][r] = 0.0f;
    float lacc[2][4] = {{0, 0, 0, 0}, {0, 0, 0, 0}};

    // per-half row indices
    int iA[2], iB[2], i1a[2], i2a[2], i1b[2], i2b[2], dA[2], dB[2];
    #pragma unroll
    for (int mh = 0; mh < 2; mh++) {
        iA[mh] = i0 + m0 + mh * 16 + g;
        iB[mh] = iA[mh] + 8;
        i1a[mh] = iA[mh] >> 5; i2a[mh] = iA[mh] & 31;
        i1b[mh] = iB[mh] >> 5; i2b[mh] = iB[mh] & 31;
        dA[mh] = i2a[mh] - 2 * tg;
        dB[mh] = i2b[mh] - 2 * tg;
    }

    // preload Q fragments (fixed for all 16 iterations); group A must be done
    cp_wait1();
    __syncthreads();
    uint32_t qf[2][4][4];
    #pragma unroll
    for (int mh = 0; mh < 2; mh++)
        #pragma unroll
        for (int ks4 = 0; ks4 < 4; ks4++)
            ldsm4(qf[mh][ks4][0], qf[mh][ks4][1], qf[mh][ks4][2], qf[mh][ks4][3],
                  smem_u32(&Qs[(m0 + mh * 16 + (lane & 15)) * 72 + ks4 * 16 + (lane >> 4) * 8]));

    for (int it = 0; it < 16; it++) {
        if (it == 15) cp_wait0(); else cp_wait1();
        __syncthreads();
        if (it < 14) {
            int st = (it + 2) % 3;
            int j0n = (it + 2) * 64;
            #pragma unroll
            for (int t = 0; t < 4; t++) {
                int e = tid + t * 128;
                int j = e >> 3, seg = e & 7;
                cp16(&Kb[st * 64 * 72 + j * 72 + seg * 8], Kg + (size_t)(j0n + j) * R3_ + seg * 8);
                cp16(&Vb[st * 64 * 72 + j * 72 + seg * 8], Vg + (size_t)(j0n + j) * R3_ + seg * 8);
            }
            cp_commit();
        }
        int cur = it % 3;
        const __nv_bfloat16* Ks = Kb + cur * 64 * 72;
        const __nv_bfloat16* Vs = Vb + cur * 64 * 72;

        // ---- init S accumulators from bias (float2 pair loads) ----
        float s[2][8][4];
        #pragma unroll
        for (int mh = 0; mh < 2; mh++) {
            const float2* RA0 = Rp + (((i1a[mh] - 2 * it)     & 31) << 5);
            const float2* RA1 = Rp + (((i1a[mh] - 2 * it - 1) & 31) << 5);
            const float2* RB0 = Rp + (((i1b[mh] - 2 * it)     & 31) << 5);
            const float2* RB1 = Rp + (((i1b[mh] - 2 * it - 1) & 31) << 5);
            #pragma unroll
            for (int jt = 0; jt < 8; jt++) {
                const float2* ra = (jt < 4) ? RA0 : RA1;
                const float2* rb = (jt < 4) ? RB0 : RB1;
                int k8 = (jt & 3) * 8;
                float2 va = ra[(dA[mh] - k8) & 31];
                float2 vb = rb[(dB[mh] - k8) & 31];
                s[mh][jt][0] = va.x; s[mh][jt][1] = va.y;
                s[mh][jt][2] = vb.x; s[mh][jt][3] = vb.y;
            }
        }

        // ---- S += Q K^T (K fragments shared by both m-halves) ----
        #pragma unroll
        for (int ks4 = 0; ks4 < 4; ks4++) {
            #pragma unroll
            for (int ntp = 0; ntp < 4; ntp++) {
                uint32_t b0, b1, b2, b3;
                int row = ntp * 16 + (lane & 7) + ((lane >> 4) << 3);   // j
                int col = ks4 * 16 + ((lane >> 3) & 1) * 8;             // d
                ldsm4(b0, b1, b2, b3, smem_u32(&Ks[row * 72 + col]));
                #pragma unroll
                for (int mh = 0; mh < 2; mh++) {
                    mma_bf16(s[mh][2 * ntp],     qf[mh][ks4], b0, b1);
                    mma_bf16(s[mh][2 * ntp + 1], qf[mh][ks4], b2, b3);
                }
            }
        }

        // ---- exp via bf16x2; l via ones-mma; O += P V (V frags shared) ----
        #pragma unroll
        for (int kq = 0; kq < 4; kq++) {
            uint32_t a2[2][4];
            #pragma unroll
            for (int mh = 0; mh < 2; mh++) {
                a2[mh][0] = ex2_bf16x2(pack_bf16(s[mh][2 * kq][0],     s[mh][2 * kq][1]));
                a2[mh][1] = ex2_bf16x2(pack_bf16(s[mh][2 * kq][2],     s[mh][2 * kq][3]));
                a2[mh][2] = ex2_bf16x2(pack_bf16(s[mh][2 * kq + 1][0], s[mh][2 * kq + 1][1]));
                a2[mh][3] = ex2_bf16x2(pack_bf16(s[mh][2 * kq + 1][2], s[mh][2 * kq + 1][3]));
                mma_bf16(lacc[mh], a2[mh], ONESB, ONESB);
            }
            #pragma unroll
            for (int dtp = 0; dtp < 4; dtp++) {
                uint32_t b0, b1, b2, b3;
                int row = kq * 16 + (lane & 7) + ((lane >> 3) & 1) * 8;  // j
                int col = (2 * dtp + (lane >> 4)) * 8;                   // d
                ldsm4t(b0, b1, b2, b3, smem_u32(&Vs[row * 72 + col]));
                #pragma unroll
                for (int mh = 0; mh < 2; mh++) {
                    mma_bf16(o[mh][2 * dtp],     a2[mh], b0, b1);
                    mma_bf16(o[mh][2 * dtp + 1], a2[mh], b2, b3);
                }
            }
        }
    }

    // ---- normalize and store ----
    __nv_bfloat16* ab = g_att + (size_t)b * N_ * HD_;
    #pragma unroll
    for (int mh = 0; mh < 2; mh++) {
        float invA = 1.0f / lacc[mh][0], invB = 1.0f / lacc[mh][2];
        #pragma unroll
        for (int dt = 0; dt < 8; dt++) {
            int col = h * DK_ + dt * 8 + 2 * tg;
            *(uint32_t*)&ab[(size_t)iA[mh] * HD_ + col] =
                pack_bf16(o[mh][dt][0] * invA, o[mh][dt][1] * invA);
            *(uint32_t*)&ab[(size_t)iB[mh] * HD_ + col] =
                pack_bf16(o[mh][dt][2] * invB, o[mh][dt][3] * invB);
        }
    }
}

// ---------------------------------------------------------------------------
// Kernel C: out[b][c][n] = W0[c] . att[b][n] + x[b][c][n]
// ---------------------------------------------------------------------------
__global__ __launch_bounds__(256, 2) void out_kernel(
    const float* __restrict__ x,
    float* __restrict__ out)
{
    extern __shared__ __align__(16) char smo[];
    __nv_bfloat16* W0s = (__nv_bfloat16*)smo;    // 2 x [128][72]
    __nv_bfloat16* As  = W0s + 2 * 128 * 72;     // 2 x [128][72]

    int tid = threadIdx.x, lane = tid & 31, w = tid >> 5;
    int g = lane >> 2, tg = lane & 3;
    int mw = w & 3, nw = w >> 2;
    int n0 = blockIdx.x * 128, b = blockIdx.y;

    const __nv_bfloat16* ab = g_att + (size_t)b * N_ * HD_;

    #pragma unroll
    for (int t = 0; t < 4; t++) {
        int e = tid + t * 256;
        int r = e >> 3, seg = e & 7;
        cp16(&W0s[r * 72 + seg * 8], g_w0b + (size_t)r * HD_ + seg * 8);
        cp16(&As[r * 72 + seg * 8],  ab + (size_t)(n0 + r) * HD_ + seg * 8);
    }
    cp_commit();

    float acc[2][8][4];
    #pragma unroll
    for (int i = 0; i < 2; i++)
        #pragma unroll
        for (int j = 0; j < 8; j++)
            #pragma unroll
            for (int k = 0; k < 4; k++) acc[i][j][k] = 0.0f;

    for (int kc = 0; kc < 8; kc++) {
        cp_wait0();
        __syncthreads();
        int cur = kc & 1;
        if (kc < 7) {
            int nb = cur ^ 1;
            int k0n = (kc + 1) * 64;
            #pragma unroll
            for (int t = 0; t < 4; t++) {
                int e = tid + t * 256;
                int r = e >> 3, seg = e & 7;
                cp16(&W0s[nb * 128 * 72 + r * 72 + seg * 8],
                     g_w0b + (size_t)r * HD_ + k0n + seg * 8);
                cp16(&As[nb * 128 * 72 + r * 72 + seg * 8],
                     ab + (size_t)(n0 + r) * HD_ + k0n + seg * 8);
            }
            cp_commit();
        }
        const __nv_bfloat16* Wc = W0s + cur * 128 * 72;
        const __nv_bfloat16* Ac = As  + cur * 128 * 72;

        #pragma unroll
        for (int ks = 0; ks < 64; ks += 16) {
            uint32_t a[2][4];
            #pragma unroll
            for (int mt = 0; mt < 2; mt++) {
                int row = mw * 32 + mt * 16 + (lane & 15);
                int col = ks + (lane >> 4) * 8;
                ldsm4(a[mt][0], a[mt][1], a[mt][2], a[mt][3], smem_u32(&Wc[row * 72 + col]));
            }
            #pragma unroll
            for (int ntp = 0; ntp < 4; ntp++) {
                uint32_t b0, b1, b2, b3;
                int row = nw * 64 + ntp * 16 + (lane & 7) + ((lane >> 4) << 3);  // n
                int col = ks + ((lane >> 3) & 1) * 8;                            // k
                ldsm4(b0, b1, b2, b3, smem_u32(&Ac[row * 72 + col]));
                #pragma unroll
                for (int mt = 0; mt < 2; mt++) {
                    mma_bf16(acc[mt][2 * ntp],     a[mt], b0, b1);
                    mma_bf16(acc[mt][2 * ntp + 1], a[mt], b2, b3);
                }
            }
        }
    }

    const float* xb = x + (size_t)b * C_ * N_;
    float* ob = out + (size_t)b * C_ * N_;
    #pragma unroll
    for (int mt = 0; mt < 2; mt++) {
        int row_a = mw * 32 + mt * 16 + g;
        #pragma unroll
        for (int nt = 0; nt < 8; nt++) {
            int col = n0 + nw * 64 + nt * 8 + 2 * tg;
            float2 xa = *(const float2*)&xb[(size_t)row_a * N_ + col];
            float2 va = make_float2(acc[mt][nt][0] + xa.x, acc[mt][nt][1] + xa.y);
            *(float2*)&ob[(size_t)row_a * N_ + col] = va;
            float2 xbv = *(const float2*)&xb[(size_t)(row_a + 8) * N_ + col];
            float2 vb = make_float2(acc[mt][nt][2] + xbv.x, acc[mt][nt][3] + xbv.y);
            *(float2*)&ob[(size_t)(row_a + 8) * N_ + col] = vb;
        }
    }
}

// ---------------------------------------------------------------------------
extern "C" void kernel_launch(void* const* d_in, const int* in_sizes, int n_in,
                              void* d_out, int out_size)
{
    const float* x  = (const float*)d_in[0];
    const float* Wq = (const float*)d_in[1];
    const float* Wk = (const float*)d_in[2];
    const float* Wv = (const float*)d_in[3];
    const float* R  = (const float*)d_in[4];
    const float* W0 = (const float*)d_in[5];
    float* out = (float*)d_out;

    const int QKV_SMEM  = (2 * 64 * 136 + 2 * 128 * 72) * 2;            // 71680 B
    const int ATTN_SMEM = (128 * 72 + 6 * 64 * 72) * 2 + 32 * 32 * 8;   // 81920 B
    const int OUT_SMEM  = (4 * 128 * 72) * 2;                           // 73728 B
    cudaFuncSetAttribute(qkv_kernel,  cudaFuncAttributeMaxDynamicSharedMemorySize, QKV_SMEM);
    cudaFuncSetAttribute(attn_kernel, cudaFuncAttributeMaxDynamicSharedMemorySize, ATTN_SMEM);
    cudaFuncSetAttribute(out_kernel,  cudaFuncAttributeMaxDynamicSharedMemorySize, OUT_SMEM);

    prep_x<<<2048, 256>>>(x);
    prep_w<<<128, 256>>>(Wq, Wk, Wv, W0);
    qkv_kernel<<<dim3(8, 12, 32), 256, QKV_SMEM>>>();
    attn_kernel<<<dim3(8, 8, 32), 128, ATTN_SMEM>>>(R);
    out_kernel<<<dim3(8, 32), 256, OUT_SMEM>>>(x, out);
}